// round 9
// baseline (speedup 1.0000x reference)
#include <cuda_runtime.h>
#include <cuda_bf16.h>
#include <cstdint>

// ---------------- scratch ----------------
__device__ __align__(16) float g_T1[4 * 132 * 64];
__device__ __align__(16) float g_GI[100 * 384];
__device__ __align__(16) float g_ht[8192 * 128];
__device__ __align__(16) float g_x[8192 * 128];
__device__ __align__(16) float g_wihT[512 * 128];
__device__ __align__(16) float g_whhT[512 * 128];
__device__ __align__(16) float g_aw1T[256 * 256];
__device__ __align__(16) float g_cw1T[256 * 256];
__device__ __align__(16) float g_w2T[64 * 256];
__device__ __align__(16) float g_w3T[128 * 256];
// GRU whh as mma.sync A-fragments: [g][mb][ks][lane][4], packed bf16x2
__device__ __align__(16) uint32_t g_wfragHi[3 * 8 * 8 * 32 * 4];
__device__ __align__(16) uint32_t g_wfragLo[3 * 8 * 8 * 32 * 4];

__device__ __forceinline__ float sigm_(float x) { return 1.0f / (1.0f + __expf(-x)); }
__device__ __forceinline__ float tanh_(float x) { return 2.0f / (1.0f + __expf(-2.0f * x)) - 1.0f; }

__device__ __forceinline__ void mma_bf16(float* d, const uint32_t* a, uint32_t b0, uint32_t b1) {
    asm volatile("mma.sync.aligned.m16n8k16.row.col.f32.bf16.bf16.f32 "
        "{%0,%1,%2,%3}, {%4,%5,%6,%7}, {%8,%9}, {%0,%1,%2,%3};"
        : "+f"(d[0]), "+f"(d[1]), "+f"(d[2]), "+f"(d[3])
        : "r"(a[0]), "r"(a[1]), "r"(a[2]), "r"(a[3]), "r"(b0), "r"(b1));
}

// ---------------- K0: transpose prep ----------------
__global__ void k_prep(const float* __restrict__ lwih, const float* __restrict__ lwhh,
                       const float* __restrict__ aw1, const float* __restrict__ cw1,
                       const float* __restrict__ c2w, const float* __restrict__ c3w) {
    int m = blockIdx.y;
    const float* src; float* dst; int N, K;
    switch (m) {
        case 0: src = lwih; dst = g_wihT; N = 512; K = 128; break;
        case 1: src = lwhh; dst = g_whhT; N = 512; K = 128; break;
        case 2: src = aw1;  dst = g_aw1T; N = 256; K = 256; break;
        case 3: src = cw1;  dst = g_cw1T; N = 256; K = 256; break;
        case 4: src = c2w;  dst = g_w2T;  N = 64;  K = 256; break;
        default:src = c3w;  dst = g_w3T;  N = 128; K = 256; break;
    }
    int total = N * K;
    for (int idx = blockIdx.x * blockDim.x + threadIdx.x; idx < total;
         idx += gridDim.x * blockDim.x) {
        int j = idx / K, k = idx % K;
        dst[(k >> 2) * (N * 4) + j * 4 + (k & 3)] = src[idx];
    }
}

// ---------------- K0b: whh -> mma.sync A fragments (split bf16) ----------------
__global__ void k_prep_frag(const float* __restrict__ gwhh) {
    int idx = blockIdx.x * blockDim.x + threadIdx.x;
    if (idx >= 24576) return;
    int r = idx & 3, lane = (idx >> 2) & 31, ks = (idx >> 7) & 7;
    int mb = (idx >> 10) & 7, g = idx >> 13;
    int gid = lane >> 2, tig = lane & 3;
    int row = mb * 16 + gid + ((r & 1) ? 8 : 0);
    int col = ks * 16 + tig * 2 + ((r & 2) ? 8 : 0);
    float w0 = gwhh[(g * 128 + row) * 128 + col];
    float w1 = gwhh[(g * 128 + row) * 128 + col + 1];
    __nv_bfloat16 h0 = __float2bfloat16(w0), h1 = __float2bfloat16(w1);
    __nv_bfloat16 l0 = __float2bfloat16(w0 - __bfloat162float(h0));
    __nv_bfloat16 l1 = __float2bfloat16(w1 - __bfloat162float(h1));
    uint16_t a, b;
    a = *(uint16_t*)&h0; b = *(uint16_t*)&h1;
    g_wfragHi[idx] = (uint32_t)a | ((uint32_t)b << 16);
    a = *(uint16_t*)&l0; b = *(uint16_t*)&l1;
    g_wfragLo[idx] = (uint32_t)a | ((uint32_t)b << 16);
}

// ---------------- K1: conv1 tap table ----------------
__global__ void k_build_t1(const float* __restrict__ obj_emb, const float* __restrict__ col_emb,
                           const float* __restrict__ st_emb, const float* __restrict__ w1) {
    int blk = blockIdx.x;
    int tap = blk / 132, combo = blk % 132;
    int ty = tap >> 1, tx = tap & 1;
    int s = combo & 1, q = combo >> 1;
    int cc = q % 6, o = q / 6;
    __shared__ __align__(16) float ev[48];
    int t = threadIdx.x;
    if (t < 16)       ev[t] = col_emb[cc * 16 + t];
    else if (t < 32)  ev[t] = obj_emb[o * 16 + (t - 16)];
    else if (t < 48)  ev[t] = st_emb[s * 16 + (t - 32)];
    __syncthreads();
    float v = 0.f;
    #pragma unroll 8
    for (int k = 0; k < 48; k++) v += w1[((t * 48 + k) * 2 + ty) * 2 + tx] * ev[k];
    g_T1[(tap * 132 + combo) * 64 + t] = v;
}

// ---------------- K2: GRU input proj table ----------------
__global__ void k_build_gi(const float* __restrict__ word_emb, const float* __restrict__ gwih,
                           const float* __restrict__ gbih) {
    int v = blockIdx.x, g = threadIdx.x;
    __shared__ __align__(16) float ev[32];
    if (g < 32) ev[g] = word_emb[v * 32 + g];
    __syncthreads();
    float a = gbih[g];
    const float* w = gwih + g * 32;
    #pragma unroll 8
    for (int k = 0; k < 32; k++) a += w[k] * ev[k];
    g_GI[v * 384 + g] = a;
}

// ---------------- K3: conv stack ----------------
__global__ __launch_bounds__(256)
void k_conv(const int* __restrict__ image, const float* __restrict__ b1,
            const float* __restrict__ b2, const float* __restrict__ b3) {
    int t = threadIdx.x;
    int half = t >> 7, st = t & 127;
    int b = blockIdx.x * 2 + half;
    __shared__ __align__(16) int   s_combo[2][49];
    __shared__ __align__(16) float s_c1[2][36 * 64];
    __shared__ __align__(16) float s_p[2][9 * 64];
    __shared__ __align__(16) float s_q[2][4 * 64];

    if (t < 98) {
        int h2 = t / 49, li = t % 49;
        const int* px = image + ((blockIdx.x * 2 + h2) * 49 + li) * 3;
        s_combo[h2][li] = (px[0] * 6 + px[1]) * 2 + px[2];
    }
    __syncthreads();
    for (int idx = st; idx < 36 * 64; idx += 128) {
        int c = idx & 63, pos = idx >> 6;
        int y = pos / 6, x = pos % 6;
        float v = b1[c];
        v += g_T1[(0 * 132 + s_combo[half][y * 7 + x]) * 64 + c];
        v += g_T1[(1 * 132 + s_combo[half][y * 7 + x + 1]) * 64 + c];
        v += g_T1[(2 * 132 + s_combo[half][(y + 1) * 7 + x]) * 64 + c];
        v += g_T1[(3 * 132 + s_combo[half][(y + 1) * 7 + x + 1]) * 64 + c];
        s_c1[half][pos * 64 + c] = fmaxf(v, 0.f);
    }
    __syncthreads();
    for (int idx = st; idx < 9 * 64; idx += 128) {
        int c = idx & 63, pos = idx >> 6;
        int y = pos / 3, x = pos % 3;
        int p0 = (2 * y) * 6 + 2 * x;
        s_p[half][pos * 64 + c] =
            fmaxf(fmaxf(s_c1[half][p0 * 64 + c], s_c1[half][(p0 + 1) * 64 + c]),
                  fmaxf(s_c1[half][(p0 + 6) * 64 + c], s_c1[half][(p0 + 7) * 64 + c]));
    }
    __syncthreads();
    for (int idx = st; idx < 256; idx += 128) {
        int c = idx & 63, pos = idx >> 6;
        int y = pos >> 1, x = pos & 1;
        float v = b2[c];
        int p00 = y * 3 + x;
        #pragma unroll 8
        for (int ci = 0; ci < 64; ci++) {
            float4 w4 = *(const float4*)(g_w2T + ci * 256 + c * 4);
            v += w4.x * s_p[half][p00 * 64 + ci] + w4.y * s_p[half][(p00 + 1) * 64 + ci]
               + w4.z * s_p[half][(p00 + 3) * 64 + ci] + w4.w * s_p[half][(p00 + 4) * 64 + ci];
        }
        s_q[half][pos * 64 + c] = fmaxf(v, 0.f);
    }
    __syncthreads();
    {
        float v = b3[st];
        #pragma unroll 8
        for (int ci = 0; ci < 64; ci++) {
            float4 w4 = *(const float4*)(g_w3T + ci * 512 + st * 4);
            v += w4.x * s_q[half][0 * 64 + ci] + w4.y * s_q[half][1 * 64 + ci]
               + w4.z * s_q[half][2 * 64 + ci] + w4.w * s_q[half][3 * 64 + ci];
        }
        g_x[b * 128 + st] = fmaxf(v, 0.f);
    }
}

// ---------------- K4: LSTM (8 elems/block, float4) ----------------
__global__ __launch_bounds__(128)
void k_lstm(const float* __restrict__ memory, const float* __restrict__ bih,
            const float* __restrict__ bhh, float* __restrict__ mem_out) {
    int j = threadIdx.x;
    int b0 = blockIdx.x * 8;
    __shared__ __align__(16) float s_x[8 * 128];
    __shared__ __align__(16) float s_h[8 * 128];
    for (int idx = j; idx < 8 * 128; idx += 128) {
        int bi = idx >> 7, k = idx & 127;
        s_x[idx] = g_x[(b0 + bi) * 128 + k];
        s_h[idx] = memory[(b0 + bi) * 256 + k];
    }
    float a0[8], a1[8], a2[8], a3[8];
    float bb0 = bih[j] + bhh[j], bb1 = bih[128 + j] + bhh[128 + j];
    float bb2 = bih[256 + j] + bhh[256 + j], bb3 = bih[384 + j] + bhh[384 + j];
    #pragma unroll
    for (int bi = 0; bi < 8; bi++) { a0[bi] = bb0; a1[bi] = bb1; a2[bi] = bb2; a3[bi] = bb3; }
    __syncthreads();
    for (int k = 0; k < 128; k += 4) {
        int kc = k >> 2;
        float4 wi0 = *(const float4*)(g_wihT + kc * 2048 + j * 4);
        float4 wi1 = *(const float4*)(g_wihT + kc * 2048 + (128 + j) * 4);
        float4 wi2 = *(const float4*)(g_wihT + kc * 2048 + (256 + j) * 4);
        float4 wi3 = *(const float4*)(g_wihT + kc * 2048 + (384 + j) * 4);
        float4 wh0 = *(const float4*)(g_whhT + kc * 2048 + j * 4);
        float4 wh1 = *(const float4*)(g_whhT + kc * 2048 + (128 + j) * 4);
        float4 wh2 = *(const float4*)(g_whhT + kc * 2048 + (256 + j) * 4);
        float4 wh3 = *(const float4*)(g_whhT + kc * 2048 + (384 + j) * 4);
        #pragma unroll
        for (int bi = 0; bi < 8; bi++) {
            float4 xv = *(const float4*)(s_x + bi * 128 + k);
            float4 hv = *(const float4*)(s_h + bi * 128 + k);
            a0[bi] += wi0.x*xv.x + wi0.y*xv.y + wi0.z*xv.z + wi0.w*xv.w
                    + wh0.x*hv.x + wh0.y*hv.y + wh0.z*hv.z + wh0.w*hv.w;
            a1[bi] += wi1.x*xv.x + wi1.y*xv.y + wi1.z*xv.z + wi1.w*xv.w
                    + wh1.x*hv.x + wh1.y*hv.y + wh1.z*hv.z + wh1.w*hv.w;
            a2[bi] += wi2.x*xv.x + wi2.y*xv.y + wi2.z*xv.z + wi2.w*xv.w
                    + wh2.x*hv.x + wh2.y*hv.y + wh2.z*hv.z + wh2.w*hv.w;
            a3[bi] += wi3.x*xv.x + wi3.y*xv.y + wi3.z*xv.z + wi3.w*xv.w
                    + wh3.x*hv.x + wh3.y*hv.y + wh3.z*hv.z + wh3.w*hv.w;
        }
    }
    #pragma unroll
    for (int bi = 0; bi < 8; bi++) {
        float c_in = memory[(b0 + bi) * 256 + 128 + j];
        float cn = sigm_(a1[bi]) * c_in + sigm_(a0[bi]) * tanh_(a2[bi]);
        float hn = sigm_(a3[bi]) * tanh_(cn);
        mem_out[(b0 + bi) * 256 + j] = hn;
        mem_out[(b0 + bi) * 256 + 128 + j] = cn;
    }
}

// ---------------- K5: mma.sync GRU (16 batch/block, 256 thr) ----------------
// smem: WHI frag 98304 | WLO frag 98304 | BHI 4096 | BLO 4096 | GI 25088 | W 1280
static constexpr int GS_WHI = 0;
static constexpr int GS_WLO = 98304;
static constexpr int GS_BHI = 196608;
static constexpr int GS_BLO = 200704;
static constexpr int GS_GI  = 204800;
static constexpr int GS_W   = 229888;
static constexpr int GS_SZ  = 231168;

__global__ __launch_bounds__(256)
void k_gru_mma(const int* __restrict__ text, const float* __restrict__ gbhh) {
    extern __shared__ __align__(16) char smem[];
    int tid = threadIdx.x;
    int w = tid >> 5, lane = tid & 31;
    int gid = lane >> 2, tig = lane & 3;
    int b0 = blockIdx.x * 16;

    // stage W fragments (192KB) + zero h tiles + stage words
    {
        const uint4* s1 = (const uint4*)g_wfragHi;
        const uint4* s2 = (const uint4*)g_wfragLo;
        uint4* d1 = (uint4*)(smem + GS_WHI);
        uint4* d2 = (uint4*)(smem + GS_WLO);
        for (int i = tid; i < 6144; i += 256) { d1[i] = s1[i]; d2[i] = s2[i]; }
        uint32_t* bz = (uint32_t*)(smem + GS_BHI);
        for (int i = tid; i < 2048; i += 256) bz[i] = 0;
        int* sw = (int*)(smem + GS_W);
        for (int i = tid; i < 320; i += 256) sw[i] = text[b0 * 20 + i];
    }
    float bh[3][2];
    {
        int j0 = w * 16 + gid;
        #pragma unroll
        for (int g = 0; g < 3; g++) {
            bh[g][0] = gbhh[g * 128 + j0];
            bh[g][1] = gbhh[g * 128 + j0 + 8];
        }
    }
    __syncthreads();

    const uint32_t* bhi = (const uint32_t*)(smem + GS_BHI);
    const uint32_t* blo = (const uint32_t*)(smem + GS_BLO);
    float* s_gi = (float*)(smem + GS_GI);
    const int* sw = (const int*)(smem + GS_W);

    for (int tt = 0; tt < 20; tt++) {
        // stage gi for this step (fp32, padded rows of 392)
        for (int i = tid; i < 6144; i += 256) {
            int n = i / 384, c = i - n * 384;
            s_gi[n * 392 + c] = g_GI[sw[n * 20 + tt] * 384 + c];
        }
        // MMAs: D[g][nt] (3 gates x 2 n-tiles x 4 regs)
        float D[3][2][4];
        #pragma unroll
        for (int g = 0; g < 3; g++)
            #pragma unroll
            for (int nt = 0; nt < 2; nt++)
                #pragma unroll
                for (int r = 0; r < 4; r++) D[g][nt][r] = 0.f;

        #pragma unroll
        for (int ks = 0; ks < 8; ks++) {
            int kp0 = ks * 8 + tig, kp1 = kp0 + 4;
            uint32_t bh0[2], bh1[2], bl0[2], bl1[2];
            #pragma unroll
            for (int nt = 0; nt < 2; nt++) {
                int n = nt * 8 + gid;
                bh0[nt] = bhi[kp0 * 16 + n]; bh1[nt] = bhi[kp1 * 16 + n];
                bl0[nt] = blo[kp0 * 16 + n]; bl1[nt] = blo[kp1 * 16 + n];
            }
            #pragma unroll
            for (int g = 0; g < 3; g++) {
                uint32_t Ah[4], Al[4];
                uint32_t foff = (((uint32_t)(g * 8 + w) * 8 + ks) << 9) + lane * 16;
                *(uint4*)Ah = *(const uint4*)(smem + GS_WHI + foff);
                *(uint4*)Al = *(const uint4*)(smem + GS_WLO + foff);
                #pragma unroll
                for (int nt = 0; nt < 2; nt++) {
                    mma_bf16(D[g][nt], Ah, bh0[nt], bh1[nt]);
                    mma_bf16(D[g][nt], Ah, bl0[nt], bl1[nt]);
                    mma_bf16(D[g][nt], Al, bh0[nt], bh1[nt]);
                }
            }
        }
        __syncthreads();   // MMA reads of B done; gi staged

        // epilogue: thread owns (j = w*16+gid+{0,8}, n = nt*8+tig*2+{0,1})
        #pragma unroll
        for (int nt = 0; nt < 2; nt++) {
            #pragma unroll
            for (int c = 0; c < 2; c++) {
                #pragma unroll
                for (int jj = 0; jj < 2; jj++) {
                    int n = nt * 8 + tig * 2 + c;
                    int j = w * 16 + gid + jj * 8;
                    int reg = jj * 2 + c;
                    uint32_t boff = (uint32_t)((j >> 1) * 16 + n) * 4 + (uint32_t)(j & 1) * 2;
                    float hp = __bfloat162float(*(__nv_bfloat16*)(smem + GS_BHI + boff))
                             + __bfloat162float(*(__nv_bfloat16*)(smem + GS_BLO + boff));
                    const float* gi = s_gi + n * 392;
                    float r = sigm_(gi[j] + bh[0][jj] + D[0][nt][reg]);
                    float z = sigm_(gi[128 + j] + bh[1][jj] + D[1][nt][reg]);
                    float nv = tanh_(gi[256 + j] + r * (bh[2][jj] + D[2][nt][reg]));
                    float h = (1.f - z) * nv + z * hp;
                    __nv_bfloat16 hhi = __float2bfloat16(h);
                    *(__nv_bfloat16*)(smem + GS_BHI + boff) = hhi;
                    *(__nv_bfloat16*)(smem + GS_BLO + boff) =
                        __float2bfloat16(h - __bfloat162float(hhi));
                    if (tt == 19) g_ht[(b0 + n) * 128 + j] = h;
                }
            }
        }
        __syncthreads();   // h writes visible for next step
    }
}

// ---------------- K6: heads (16 batch/block) ----------------
__global__ __launch_bounds__(256)
void k_heads(const float* __restrict__ mem, const float* __restrict__ ab1,
             const float* __restrict__ aw2, const float* __restrict__ ab2,
             const float* __restrict__ cb1, const float* __restrict__ cw2,
             const float* __restrict__ cb2, float* __restrict__ lp, float* __restrict__ value) {
    int tid = threadIdx.x;
    int b0 = blockIdx.x * 16;
    __shared__ __align__(16) float s_emb[16 * 256];
    __shared__ __align__(16) float s_a1[16 * 256];
    __shared__ __align__(16) float s_logits[16 * 8];

    for (int idx = tid; idx < 16 * 128; idx += 256) {
        int bi = idx >> 7, k = idx & 127;
        s_emb[bi * 256 + k]       = mem[(b0 + bi) * 256 + k];
        s_emb[bi * 256 + 128 + k] = g_ht[(b0 + bi) * 128 + k];
    }
    __syncthreads();
    {
        float acc[16];
        float bb = ab1[tid];
        #pragma unroll
        for (int bi = 0; bi < 16; bi++) acc[bi] = bb;
        for (int k = 0; k < 256; k += 4) {
            float4 w4 = *(const float4*)(g_aw1T + (k >> 2) * 1024 + tid * 4);
            #pragma unroll
            for (int bi = 0; bi < 16; bi++) {
                float4 e = *(const float4*)(s_emb + bi * 256 + k);
                acc[bi] += w4.x*e.x + w4.y*e.y + w4.z*e.z + w4.w*e.w;
            }
        }
        #pragma unroll
        for (int bi = 0; bi < 16; bi++) s_a1[bi * 256 + tid] = tanh_(acc[bi]);
    }
    __syncthreads();
    int warp = tid >> 5, lane = tid & 31;
    for (int bi = warp * 2; bi < warp * 2 + 2; bi++)
        for (int a = 0; a < 7; a++) {
            float s = 0.f;
            for (int k = lane; k < 256; k += 32) s += aw2[a * 256 + k] * s_a1[bi * 256 + k];
            #pragma unroll
            for (int off = 16; off; off >>= 1) s += __shfl_xor_sync(0xffffffffu, s, off);
            if (lane == 0) s_logits[bi * 8 + a] = s + ab2[a];
        }
    __syncthreads();
    {
        float acc[16];
        float bb = cb1[tid];
        #pragma unroll
        for (int bi = 0; bi < 16; bi++) acc[bi] = bb;
        for (int k = 0; k < 256; k += 4) {
            float4 w4 = *(const float4*)(g_cw1T + (k >> 2) * 1024 + tid * 4);
            #pragma unroll
            for (int bi = 0; bi < 16; bi++) {
                float4 e = *(const float4*)(s_emb + bi * 256 + k);
                acc[bi] += w4.x*e.x + w4.y*e.y + w4.z*e.z + w4.w*e.w;
            }
        }
        #pragma unroll
        for (int bi = 0; bi < 16; bi++) s_a1[bi * 256 + tid] = tanh_(acc[bi]);
    }
    if (tid < 16) {
        float m = -1e30f;
        #pragma unroll
        for (int a = 0; a < 7; a++) m = fmaxf(m, s_logits[tid * 8 + a]);
        float sum = 0.f;
        #pragma unroll
        for (int a = 0; a < 7; a++) sum += expf(s_logits[tid * 8 + a] - m);
        float lse = m + logf(sum);
        #pragma unroll
        for (int a = 0; a < 7; a++) lp[(b0 + tid) * 7 + a] = s_logits[tid * 8 + a] - lse;
    }
    __syncthreads();
    for (int bi = warp * 2; bi < warp * 2 + 2; bi++) {
        float s = 0.f;
        for (int k = lane; k < 256; k += 32) s += cw2[k] * s_a1[bi * 256 + k];
        #pragma unroll
        for (int off = 16; off; off >>= 1) s += __shfl_xor_sync(0xffffffffu, s, off);
        if (lane == 0) value[b0 + bi] = s + cb2[0];
    }
}

// ---------------- launch ----------------
extern "C" void kernel_launch(void* const* d_in, const int* in_sizes, int n_in,
                              void* d_out, int out_size) {
    const int*   image  = (const int*)  d_in[0];
    const float* memory = (const float*)d_in[1];
    const int*   text   = (const int*)  d_in[2];
    const float* obj_e  = (const float*)d_in[3];
    const float* col_e  = (const float*)d_in[4];
    const float* st_e   = (const float*)d_in[5];
    const float* c1w    = (const float*)d_in[6];
    const float* c1b    = (const float*)d_in[7];
    const float* c2w    = (const float*)d_in[8];
    const float* c2b    = (const float*)d_in[9];
    const float* c3w    = (const float*)d_in[10];
    const float* c3b    = (const float*)d_in[11];
    const float* lwih   = (const float*)d_in[12];
    const float* lwhh   = (const float*)d_in[13];
    const float* lbih   = (const float*)d_in[14];
    const float* lbhh   = (const float*)d_in[15];
    const float* wemb   = (const float*)d_in[16];
    const float* gwih   = (const float*)d_in[17];
    const float* gwhh   = (const float*)d_in[18];
    const float* gbih   = (const float*)d_in[19];
    const float* gbhh   = (const float*)d_in[20];
    const float* aw1    = (const float*)d_in[21];
    const float* ab1    = (const float*)d_in[22];
    const float* aw2    = (const float*)d_in[23];
    const float* ab2    = (const float*)d_in[24];
    const float* cw1    = (const float*)d_in[25];
    const float* cb1    = (const float*)d_in[26];
    const float* cw2    = (const float*)d_in[27];
    const float* cb2    = (const float*)d_in[28];

    const int B = in_sizes[1] / 256;
    float* out   = (float*)d_out;
    float* lp    = out;
    float* value = out + (size_t)B * 7;
    float* memo  = out + (size_t)B * 8;

    cudaFuncSetAttribute(k_gru_mma, cudaFuncAttributeMaxDynamicSharedMemorySize, GS_SZ);

    dim3 pgrid(64, 6);
    k_prep<<<pgrid, 256>>>(lwih, lwhh, aw1, cw1, c2w, c3w);
    k_prep_frag<<<96, 256>>>(gwhh);
    k_build_t1<<<4 * 132, 64>>>(obj_e, col_e, st_e, c1w);
    k_build_gi<<<100, 384>>>(wemb, gwih, gbih);

    k_conv<<<B / 2, 256>>>(image, c1b, c2b, c3b);
    k_lstm<<<B / 8, 128>>>(memory, lbih, lbhh, memo);
    k_gru_mma<<<B / 16, 256, GS_SZ>>>(text, gbhh);
    k_heads<<<B / 16, 256>>>(memo, ab1, aw2, ab2, cb1, cw2, cb2, lp, value);
}

// round 10
// speedup vs baseline: 1.3067x; 1.3067x over previous
#include <cuda_runtime.h>
#include <cuda_bf16.h>
#include <cstdint>

// ---------------- scratch ----------------
__device__ __align__(16) float g_T1[4 * 132 * 64];
__device__ __align__(16) float g_GI2[100 * 512];   // [word][j][4] = {r,z,n,pad}, bhh baked in
__device__ __align__(16) float g_ht[8192 * 128];
__device__ __align__(16) float g_x[8192 * 128];
__device__ __align__(16) float g_wihT[512 * 128];
__device__ __align__(16) float g_whhT[512 * 128];
__device__ __align__(16) float g_aw1T[256 * 256];
__device__ __align__(16) float g_cw1T[256 * 256];
__device__ __align__(16) float g_w2T[64 * 256];
__device__ __align__(16) float g_w3T[128 * 256];
// GRU whh as mma.sync A-fragments: [g][mb][ks][lane][4], packed bf16x2
__device__ __align__(16) uint32_t g_wfragHi[3 * 8 * 8 * 32 * 4];
__device__ __align__(16) uint32_t g_wfragLo[3 * 8 * 8 * 32 * 4];

__device__ __forceinline__ float sigm_(float x) { return 1.0f / (1.0f + __expf(-x)); }
__device__ __forceinline__ float tanh_(float x) { return 2.0f / (1.0f + __expf(-2.0f * x)) - 1.0f; }

__device__ __forceinline__ void mma_bf16(float* d, const uint32_t* a, uint32_t b0, uint32_t b1) {
    asm volatile("mma.sync.aligned.m16n8k16.row.col.f32.bf16.bf16.f32 "
        "{%0,%1,%2,%3}, {%4,%5,%6,%7}, {%8,%9}, {%0,%1,%2,%3};"
        : "+f"(d[0]), "+f"(d[1]), "+f"(d[2]), "+f"(d[3])
        : "r"(a[0]), "r"(a[1]), "r"(a[2]), "r"(a[3]), "r"(b0), "r"(b1));
}

// ---------------- K0: transpose prep ----------------
__global__ void k_prep(const float* __restrict__ lwih, const float* __restrict__ lwhh,
                       const float* __restrict__ aw1, const float* __restrict__ cw1,
                       const float* __restrict__ c2w, const float* __restrict__ c3w) {
    int m = blockIdx.y;
    const float* src; float* dst; int N, K;
    switch (m) {
        case 0: src = lwih; dst = g_wihT; N = 512; K = 128; break;
        case 1: src = lwhh; dst = g_whhT; N = 512; K = 128; break;
        case 2: src = aw1;  dst = g_aw1T; N = 256; K = 256; break;
        case 3: src = cw1;  dst = g_cw1T; N = 256; K = 256; break;
        case 4: src = c2w;  dst = g_w2T;  N = 64;  K = 256; break;
        default:src = c3w;  dst = g_w3T;  N = 128; K = 256; break;
    }
    int total = N * K;
    for (int idx = blockIdx.x * blockDim.x + threadIdx.x; idx < total;
         idx += gridDim.x * blockDim.x) {
        int j = idx / K, k = idx % K;
        dst[(k >> 2) * (N * 4) + j * 4 + (k & 3)] = src[idx];
    }
}

// ---------------- K0b: whh -> mma.sync A fragments (split bf16) ----------------
__global__ void k_prep_frag(const float* __restrict__ gwhh) {
    int idx = blockIdx.x * blockDim.x + threadIdx.x;
    if (idx >= 24576) return;
    int r = idx & 3, lane = (idx >> 2) & 31, ks = (idx >> 7) & 7;
    int mb = (idx >> 10) & 7, g = idx >> 13;
    int gid = lane >> 2, tig = lane & 3;
    int row = mb * 16 + gid + ((r & 1) ? 8 : 0);
    int col = ks * 16 + tig * 2 + ((r & 2) ? 8 : 0);
    float w0 = gwhh[(g * 128 + row) * 128 + col];
    float w1 = gwhh[(g * 128 + row) * 128 + col + 1];
    __nv_bfloat16 h0 = __float2bfloat16(w0), h1 = __float2bfloat16(w1);
    __nv_bfloat16 l0 = __float2bfloat16(w0 - __bfloat162float(h0));
    __nv_bfloat16 l1 = __float2bfloat16(w1 - __bfloat162float(h1));
    uint16_t a, b;
    a = *(uint16_t*)&h0; b = *(uint16_t*)&h1;
    g_wfragHi[idx] = (uint32_t)a | ((uint32_t)b << 16);
    a = *(uint16_t*)&l0; b = *(uint16_t*)&l1;
    g_wfragLo[idx] = (uint32_t)a | ((uint32_t)b << 16);
}

// ---------------- K1: conv1 tap table ----------------
__global__ void k_build_t1(const float* __restrict__ obj_emb, const float* __restrict__ col_emb,
                           const float* __restrict__ st_emb, const float* __restrict__ w1) {
    int blk = blockIdx.x;
    int tap = blk / 132, combo = blk % 132;
    int ty = tap >> 1, tx = tap & 1;
    int s = combo & 1, q = combo >> 1;
    int cc = q % 6, o = q / 6;
    __shared__ __align__(16) float ev[48];
    int t = threadIdx.x;
    if (t < 16)       ev[t] = col_emb[cc * 16 + t];
    else if (t < 32)  ev[t] = obj_emb[o * 16 + (t - 16)];
    else if (t < 48)  ev[t] = st_emb[s * 16 + (t - 32)];
    __syncthreads();
    float v = 0.f;
    #pragma unroll 8
    for (int k = 0; k < 48; k++) v += w1[((t * 48 + k) * 2 + ty) * 2 + tx] * ev[k];
    g_T1[(tap * 132 + combo) * 64 + t] = v;
}

// ---------------- K2: GRU input proj table ([word][j][4], bhh baked) ----------
__global__ void k_build_gi(const float* __restrict__ word_emb, const float* __restrict__ gwih,
                           const float* __restrict__ gbih, const float* __restrict__ gbhh) {
    int v = blockIdx.x, g = threadIdx.x;          // g in [0,384)
    __shared__ __align__(16) float ev[32];
    if (g < 32) ev[g] = word_emb[v * 32 + g];
    __syncthreads();
    float a = gbih[g] + gbhh[g];
    const float* w = gwih + g * 32;
    #pragma unroll 8
    for (int k = 0; k < 32; k++) a += w[k] * ev[k];
    int gate = g >> 7, j = g & 127;
    g_GI2[v * 512 + j * 4 + gate] = a;
}

// ---------------- K3: conv stack ----------------
__global__ __launch_bounds__(256)
void k_conv(const int* __restrict__ image, const float* __restrict__ b1,
            const float* __restrict__ b2, const float* __restrict__ b3) {
    int t = threadIdx.x;
    int half = t >> 7, st = t & 127;
    int b = blockIdx.x * 2 + half;
    __shared__ __align__(16) int   s_combo[2][49];
    __shared__ __align__(16) float s_c1[2][36 * 64];
    __shared__ __align__(16) float s_p[2][9 * 64];
    __shared__ __align__(16) float s_q[2][4 * 64];

    if (t < 98) {
        int h2 = t / 49, li = t % 49;
        const int* px = image + ((blockIdx.x * 2 + h2) * 49 + li) * 3;
        s_combo[h2][li] = (px[0] * 6 + px[1]) * 2 + px[2];
    }
    __syncthreads();
    for (int idx = st; idx < 36 * 64; idx += 128) {
        int c = idx & 63, pos = idx >> 6;
        int y = pos / 6, x = pos % 6;
        float v = b1[c];
        v += g_T1[(0 * 132 + s_combo[half][y * 7 + x]) * 64 + c];
        v += g_T1[(1 * 132 + s_combo[half][y * 7 + x + 1]) * 64 + c];
        v += g_T1[(2 * 132 + s_combo[half][(y + 1) * 7 + x]) * 64 + c];
        v += g_T1[(3 * 132 + s_combo[half][(y + 1) * 7 + x + 1]) * 64 + c];
        s_c1[half][pos * 64 + c] = fmaxf(v, 0.f);
    }
    __syncthreads();
    for (int idx = st; idx < 9 * 64; idx += 128) {
        int c = idx & 63, pos = idx >> 6;
        int y = pos / 3, x = pos % 3;
        int p0 = (2 * y) * 6 + 2 * x;
        s_p[half][pos * 64 + c] =
            fmaxf(fmaxf(s_c1[half][p0 * 64 + c], s_c1[half][(p0 + 1) * 64 + c]),
                  fmaxf(s_c1[half][(p0 + 6) * 64 + c], s_c1[half][(p0 + 7) * 64 + c]));
    }
    __syncthreads();
    for (int idx = st; idx < 256; idx += 128) {
        int c = idx & 63, pos = idx >> 6;
        int y = pos >> 1, x = pos & 1;
        float v = b2[c];
        int p00 = y * 3 + x;
        #pragma unroll 8
        for (int ci = 0; ci < 64; ci++) {
            float4 w4 = *(const float4*)(g_w2T + ci * 256 + c * 4);
            v += w4.x * s_p[half][p00 * 64 + ci] + w4.y * s_p[half][(p00 + 1) * 64 + ci]
               + w4.z * s_p[half][(p00 + 3) * 64 + ci] + w4.w * s_p[half][(p00 + 4) * 64 + ci];
        }
        s_q[half][pos * 64 + c] = fmaxf(v, 0.f);
    }
    __syncthreads();
    {
        float v = b3[st];
        #pragma unroll 8
        for (int ci = 0; ci < 64; ci++) {
            float4 w4 = *(const float4*)(g_w3T + ci * 512 + st * 4);
            v += w4.x * s_q[half][0 * 64 + ci] + w4.y * s_q[half][1 * 64 + ci]
               + w4.z * s_q[half][2 * 64 + ci] + w4.w * s_q[half][3 * 64 + ci];
        }
        g_x[b * 128 + st] = fmaxf(v, 0.f);
    }
}

// ---------------- K4: LSTM (8 elems/block, float4) ----------------
__global__ __launch_bounds__(128)
void k_lstm(const float* __restrict__ memory, const float* __restrict__ bih,
            const float* __restrict__ bhh, float* __restrict__ mem_out) {
    int j = threadIdx.x;
    int b0 = blockIdx.x * 8;
    __shared__ __align__(16) float s_x[8 * 128];
    __shared__ __align__(16) float s_h[8 * 128];
    for (int idx = j; idx < 8 * 128; idx += 128) {
        int bi = idx >> 7, k = idx & 127;
        s_x[idx] = g_x[(b0 + bi) * 128 + k];
        s_h[idx] = memory[(b0 + bi) * 256 + k];
    }
    float a0[8], a1[8], a2[8], a3[8];
    float bb0 = bih[j] + bhh[j], bb1 = bih[128 + j] + bhh[128 + j];
    float bb2 = bih[256 + j] + bhh[256 + j], bb3 = bih[384 + j] + bhh[384 + j];
    #pragma unroll
    for (int bi = 0; bi < 8; bi++) { a0[bi] = bb0; a1[bi] = bb1; a2[bi] = bb2; a3[bi] = bb3; }
    __syncthreads();
    for (int k = 0; k < 128; k += 4) {
        int kc = k >> 2;
        float4 wi0 = *(const float4*)(g_wihT + kc * 2048 + j * 4);
        float4 wi1 = *(const float4*)(g_wihT + kc * 2048 + (128 + j) * 4);
        float4 wi2 = *(const float4*)(g_wihT + kc * 2048 + (256 + j) * 4);
        float4 wi3 = *(const float4*)(g_wihT + kc * 2048 + (384 + j) * 4);
        float4 wh0 = *(const float4*)(g_whhT + kc * 2048 + j * 4);
        float4 wh1 = *(const float4*)(g_whhT + kc * 2048 + (128 + j) * 4);
        float4 wh2 = *(const float4*)(g_whhT + kc * 2048 + (256 + j) * 4);
        float4 wh3 = *(const float4*)(g_whhT + kc * 2048 + (384 + j) * 4);
        #pragma unroll
        for (int bi = 0; bi < 8; bi++) {
            float4 xv = *(const float4*)(s_x + bi * 128 + k);
            float4 hv = *(const float4*)(s_h + bi * 128 + k);
            a0[bi] += wi0.x*xv.x + wi0.y*xv.y + wi0.z*xv.z + wi0.w*xv.w
                    + wh0.x*hv.x + wh0.y*hv.y + wh0.z*hv.z + wh0.w*hv.w;
            a1[bi] += wi1.x*xv.x + wi1.y*xv.y + wi1.z*xv.z + wi1.w*xv.w
                    + wh1.x*hv.x + wh1.y*hv.y + wh1.z*hv.z + wh1.w*hv.w;
            a2[bi] += wi2.x*xv.x + wi2.y*xv.y + wi2.z*xv.z + wi2.w*xv.w
                    + wh2.x*hv.x + wh2.y*hv.y + wh2.z*hv.z + wh2.w*hv.w;
            a3[bi] += wi3.x*xv.x + wi3.y*xv.y + wi3.z*xv.z + wi3.w*xv.w
                    + wh3.x*hv.x + wh3.y*hv.y + wh3.z*hv.z + wh3.w*hv.w;
        }
    }
    #pragma unroll
    for (int bi = 0; bi < 8; bi++) {
        float c_in = memory[(b0 + bi) * 256 + 128 + j];
        float cn = sigm_(a1[bi]) * c_in + sigm_(a0[bi]) * tanh_(a2[bi]);
        float hn = sigm_(a3[bi]) * tanh_(cn);
        mem_out[(b0 + bi) * 256 + j] = hn;
        mem_out[(b0 + bi) * 256 + 128 + j] = cn;
    }
}

// ---------------- K5: mma.sync GRU (64 batch/block, 256 thr, 1 wave) ----------
// smem: WHI 98304 | WLO 98304 | BHI [64][68]u32 17408 | BLO 17408  = 231424
static constexpr int GQ_WHI = 0;
static constexpr int GQ_WLO = 98304;
static constexpr int GQ_BHI = 196608;
static constexpr int GQ_BLO = 196608 + 17408;
static constexpr int GQ_SZ  = 196608 + 34816;

__global__ __launch_bounds__(256, 1)
void k_gru_mma(const int* __restrict__ text) {
    extern __shared__ __align__(16) char smem[];
    int tid = threadIdx.x;
    int w = tid >> 5, lane = tid & 31;
    int gid = lane >> 2, tig = lane & 3;
    int b0 = blockIdx.x * 64;

    {   // stage W fragments (192KB) + zero h tiles
        const uint4* s1 = (const uint4*)g_wfragHi;
        const uint4* s2 = (const uint4*)g_wfragLo;
        uint4* d1 = (uint4*)(smem + GQ_WHI);
        uint4* d2 = (uint4*)(smem + GQ_WLO);
        for (int i = tid; i < 6144; i += 256) { d1[i] = s1[i]; d2[i] = s2[i]; }
        uint4 z = make_uint4(0, 0, 0, 0);
        uint4* dz = (uint4*)(smem + GQ_BHI);
        for (int i = tid; i < 2176; i += 256) dz[i] = z;
    }
    __syncthreads();

    const uint32_t* bhi = (const uint32_t*)(smem + GQ_BHI);
    const uint32_t* blo = (const uint32_t*)(smem + GQ_BLO);

    for (int tt = 0; tt < 20; tt++) {
        float D[3][8][4];
        #pragma unroll
        for (int g = 0; g < 3; g++)
            #pragma unroll
            for (int nt = 0; nt < 8; nt++)
                #pragma unroll
                for (int r = 0; r < 4; r++) D[g][nt][r] = 0.f;

        #pragma unroll
        for (int ks = 0; ks < 8; ks++) {
            uint32_t B0h[8], B1h[8], B0l[8], B1l[8];
            #pragma unroll
            for (int nt = 0; nt < 8; nt++) {
                int n = nt * 8 + gid;
                int kp = ks * 8 + tig;
                B0h[nt] = bhi[n * 68 + kp];  B1h[nt] = bhi[n * 68 + kp + 4];
                B0l[nt] = blo[n * 68 + kp];  B1l[nt] = blo[n * 68 + kp + 4];
            }
            #pragma unroll
            for (int g = 0; g < 3; g++) {
                uint32_t Ah[4], Al[4];
                uint32_t foff = (((uint32_t)(g * 8 + w) * 8 + ks) << 9) + lane * 16;
                *(uint4*)Ah = *(const uint4*)(smem + GQ_WHI + foff);
                *(uint4*)Al = *(const uint4*)(smem + GQ_WLO + foff);
                #pragma unroll
                for (int nt = 0; nt < 8; nt++) {
                    mma_bf16(D[g][nt], Ah, B0h[nt], B1h[nt]);
                    mma_bf16(D[g][nt], Ah, B0l[nt], B1l[nt]);
                    mma_bf16(D[g][nt], Al, B0h[nt], B1h[nt]);
                }
            }
        }
        __syncthreads();   // all MMA reads of h done before epilogue rewrites

        #pragma unroll
        for (int nt = 0; nt < 8; nt++) {
            #pragma unroll
            for (int c = 0; c < 2; c++) {
                int n = nt * 8 + tig * 2 + c;
                int word = text[(b0 + n) * 20 + tt];
                const float4* gi4 = (const float4*)(g_GI2 + word * 512);
                #pragma unroll
                for (int jj = 0; jj < 2; jj++) {
                    int j = w * 16 + gid + jj * 8;
                    int reg = jj * 2 + c;
                    float4 gv = gi4[j];
                    uint32_t boff = (uint32_t)(n * 68 + (j >> 1)) * 4 + (uint32_t)(j & 1) * 2;
                    float hp = __bfloat162float(*(__nv_bfloat16*)(smem + GQ_BHI + boff))
                             + __bfloat162float(*(__nv_bfloat16*)(smem + GQ_BLO + boff));
                    float r = sigm_(gv.x + D[0][nt][reg]);
                    float z = sigm_(gv.y + D[1][nt][reg]);
                    float nv = tanh_(gv.z + r * D[2][nt][reg]);
                    float h = (1.f - z) * nv + z * hp;
                    __nv_bfloat16 hhi = __float2bfloat16(h);
                    *(__nv_bfloat16*)(smem + GQ_BHI + boff) = hhi;
                    *(__nv_bfloat16*)(smem + GQ_BLO + boff) =
                        __float2bfloat16(h - __bfloat162float(hhi));
                    if (tt == 19) g_ht[(b0 + n) * 128 + j] = h;
                }
            }
        }
        __syncthreads();   // h writes visible before next step's MMAs
    }
}

// ---------------- K6: heads (16 batch/block) ----------------
__global__ __launch_bounds__(256)
void k_heads(const float* __restrict__ mem, const float* __restrict__ ab1,
             const float* __restrict__ aw2, const float* __restrict__ ab2,
             const float* __restrict__ cb1, const float* __restrict__ cw2,
             const float* __restrict__ cb2, float* __restrict__ lp, float* __restrict__ value) {
    int tid = threadIdx.x;
    int b0 = blockIdx.x * 16;
    __shared__ __align__(16) float s_emb[16 * 256];
    __shared__ __align__(16) float s_a1[16 * 256];
    __shared__ __align__(16) float s_logits[16 * 8];

    for (int idx = tid; idx < 16 * 128; idx += 256) {
        int bi = idx >> 7, k = idx & 127;
        s_emb[bi * 256 + k]       = mem[(b0 + bi) * 256 + k];
        s_emb[bi * 256 + 128 + k] = g_ht[(b0 + bi) * 128 + k];
    }
    __syncthreads();
    {
        float acc[16];
        float bb = ab1[tid];
        #pragma unroll
        for (int bi = 0; bi < 16; bi++) acc[bi] = bb;
        for (int k = 0; k < 256; k += 4) {
            float4 w4 = *(const float4*)(g_aw1T + (k >> 2) * 1024 + tid * 4);
            #pragma unroll
            for (int bi = 0; bi < 16; bi++) {
                float4 e = *(const float4*)(s_emb + bi * 256 + k);
                acc[bi] += w4.x*e.x + w4.y*e.y + w4.z*e.z + w4.w*e.w;
            }
        }
        #pragma unroll
        for (int bi = 0; bi < 16; bi++) s_a1[bi * 256 + tid] = tanh_(acc[bi]);
    }
    __syncthreads();
    int warp = tid >> 5, lane = tid & 31;
    for (int bi = warp * 2; bi < warp * 2 + 2; bi++)
        for (int a = 0; a < 7; a++) {
            float s = 0.f;
            for (int k = lane; k < 256; k += 32) s += aw2[a * 256 + k] * s_a1[bi * 256 + k];
            #pragma unroll
            for (int off = 16; off; off >>= 1) s += __shfl_xor_sync(0xffffffffu, s, off);
            if (lane == 0) s_logits[bi * 8 + a] = s + ab2[a];
        }
    __syncthreads();
    {
        float acc[16];
        float bb = cb1[tid];
        #pragma unroll
        for (int bi = 0; bi < 16; bi++) acc[bi] = bb;
        for (int k = 0; k < 256; k += 4) {
            float4 w4 = *(const float4*)(g_cw1T + (k >> 2) * 1024 + tid * 4);
            #pragma unroll
            for (int bi = 0; bi < 16; bi++) {
                float4 e = *(const float4*)(s_emb + bi * 256 + k);
                acc[bi] += w4.x*e.x + w4.y*e.y + w4.z*e.z + w4.w*e.w;
            }
        }
        #pragma unroll
        for (int bi = 0; bi < 16; bi++) s_a1[bi * 256 + tid] = tanh_(acc[bi]);
    }
    if (tid < 16) {
        float m = -1e30f;
        #pragma unroll
        for (int a = 0; a < 7; a++) m = fmaxf(m, s_logits[tid * 8 + a]);
        float sum = 0.f;
        #pragma unroll
        for (int a = 0; a < 7; a++) sum += expf(s_logits[tid * 8 + a] - m);
        float lse = m + logf(sum);
        #pragma unroll
        for (int a = 0; a < 7; a++) lp[(b0 + tid) * 7 + a] = s_logits[tid * 8 + a] - lse;
    }
    __syncthreads();
    for (int bi = warp * 2; bi < warp * 2 + 2; bi++) {
        float s = 0.f;
        for (int k = lane; k < 256; k += 32) s += cw2[k] * s_a1[bi * 256 + k];
        #pragma unroll
        for (int off = 16; off; off >>= 1) s += __shfl_xor_sync(0xffffffffu, s, off);
        if (lane == 0) value[b0 + bi] = s + cb2[0];
    }
}

// ---------------- launch ----------------
extern "C" void kernel_launch(void* const* d_in, const int* in_sizes, int n_in,
                              void* d_out, int out_size) {
    const int*   image  = (const int*)  d_in[0];
    const float* memory = (const float*)d_in[1];
    const int*   text   = (const int*)  d_in[2];
    const float* obj_e  = (const float*)d_in[3];
    const float* col_e  = (const float*)d_in[4];
    const float* st_e   = (const float*)d_in[5];
    const float* c1w    = (const float*)d_in[6];
    const float* c1b    = (const float*)d_in[7];
    const float* c2w    = (const float*)d_in[8];
    const float* c2b    = (const float*)d_in[9];
    const float* c3w    = (const float*)d_in[10];
    const float* c3b    = (const float*)d_in[11];
    const float* lwih   = (const float*)d_in[12];
    const float* lwhh   = (const float*)d_in[13];
    const float* lbih   = (const float*)d_in[14];
    const float* lbhh   = (const float*)d_in[15];
    const float* wemb   = (const float*)d_in[16];
    const float* gwih   = (const float*)d_in[17];
    const float* gwhh   = (const float*)d_in[18];
    const float* gbih   = (const float*)d_in[19];
    const float* gbhh   = (const float*)d_in[20];
    const float* aw1    = (const float*)d_in[21];
    const float* ab1    = (const float*)d_in[22];
    const float* aw2    = (const float*)d_in[23];
    const float* ab2    = (const float*)d_in[24];
    const float* cw1    = (const float*)d_in[25];
    const float* cb1    = (const float*)d_in[26];
    const float* cw2    = (const float*)d_in[27];
    const float* cb2    = (const float*)d_in[28];

    const int B = in_sizes[1] / 256;
    float* out   = (float*)d_out;
    float* lp    = out;
    float* value = out + (size_t)B * 7;
    float* memo  = out + (size_t)B * 8;

    cudaFuncSetAttribute(k_gru_mma, cudaFuncAttributeMaxDynamicSharedMemorySize, GQ_SZ);

    dim3 pgrid(64, 6);
    k_prep<<<pgrid, 256>>>(lwih, lwhh, aw1, cw1, c2w, c3w);
    k_prep_frag<<<96, 256>>>(gwhh);
    k_build_t1<<<4 * 132, 64>>>(obj_e, col_e, st_e, c1w);
    k_build_gi<<<100, 384>>>(wemb, gwih, gbih, gbhh);

    k_conv<<<B / 2, 256>>>(image, c1b, c2b, c3b);
    k_lstm<<<B / 8, 128>>>(memory, lbih, lbhh, memo);
    k_gru_mma<<<B / 64, 256, GQ_SZ>>>(text);
    k_heads<<<B / 16, 256>>>(memo, ab1, aw2, ab2, cb1, cw2, cb2, lp, value);
}

// round 11
// speedup vs baseline: 1.4801x; 1.1326x over previous
#include <cuda_runtime.h>
#include <cuda_bf16.h>
#include <cstdint>

// ---------------- scratch ----------------
__device__ __align__(16) float g_T1[4 * 132 * 64];
__device__ __align__(16) float g_GI2[100 * 512];   // [word][j][4]={r,z,n,pad}, bhh baked
__device__ __align__(16) float g_ht[8192 * 128];
__device__ __align__(16) float g_x[8192 * 128];
__device__ __align__(16) float g_aw1T[256 * 256];
__device__ __align__(16) float g_cw1T[256 * 256];
__device__ __align__(16) float g_w2T[64 * 256];
__device__ __align__(16) float g_w3T[128 * 256];
// GRU whh mma fragments: [g][w][ks][lane][4] bf16x2
__device__ __align__(16) uint32_t g_wfragHi[3 * 8 * 8 * 32 * 4];
__device__ __align__(16) uint32_t g_wfragLo[3 * 8 * 8 * 32 * 4];
// LSTM [wih|whh] mma fragments: [g4][w8][ks16][lane32][4] bf16x2
__device__ __align__(16) uint32_t g_lfragHi[4 * 8 * 16 * 32 * 4];
__device__ __align__(16) uint32_t g_lfragLo[4 * 8 * 16 * 32 * 4];

__device__ __forceinline__ float sigm_(float x) { return 1.0f / (1.0f + __expf(-x)); }
__device__ __forceinline__ float tanh_(float x) { return 2.0f / (1.0f + __expf(-2.0f * x)) - 1.0f; }

__device__ __forceinline__ void mma_bf16(float* d, const uint32_t* a, uint32_t b0, uint32_t b1) {
    asm volatile("mma.sync.aligned.m16n8k16.row.col.f32.bf16.bf16.f32 "
        "{%0,%1,%2,%3}, {%4,%5,%6,%7}, {%8,%9}, {%0,%1,%2,%3};"
        : "+f"(d[0]), "+f"(d[1]), "+f"(d[2]), "+f"(d[3])
        : "r"(a[0]), "r"(a[1]), "r"(a[2]), "r"(a[3]), "r"(b0), "r"(b1));
}
__device__ __forceinline__ uint32_t packbf(float a, float b) {
    __nv_bfloat16 ha = __float2bfloat16(a), hb = __float2bfloat16(b);
    return (uint32_t)*(uint16_t*)&ha | ((uint32_t)*(uint16_t*)&hb << 16);
}

// ---------------- K0: transpose prep (heads + conv weights) ----------------
__global__ void k_prep(const float* __restrict__ aw1, const float* __restrict__ cw1,
                       const float* __restrict__ c2w, const float* __restrict__ c3w) {
    int m = blockIdx.y;
    const float* src; float* dst; int N, K;
    switch (m) {
        case 0: src = aw1; dst = g_aw1T; N = 256; K = 256; break;
        case 1: src = cw1; dst = g_cw1T; N = 256; K = 256; break;
        case 2: src = c2w; dst = g_w2T;  N = 64;  K = 256; break;
        default:src = c3w; dst = g_w3T;  N = 128; K = 256; break;
    }
    int total = N * K;
    for (int idx = blockIdx.x * blockDim.x + threadIdx.x; idx < total;
         idx += gridDim.x * blockDim.x) {
        int j = idx / K, k = idx % K;
        dst[(k >> 2) * (N * 4) + j * 4 + (k & 3)] = src[idx];
    }
}

// ---------------- K0b: GRU whh -> fragments ----------------
__global__ void k_prep_frag(const float* __restrict__ gwhh) {
    int idx = blockIdx.x * blockDim.x + threadIdx.x;
    if (idx >= 24576) return;
    int r = idx & 3, lane = (idx >> 2) & 31, ks = (idx >> 7) & 7;
    int w = (idx >> 10) & 7, g = idx >> 13;
    int gid = lane >> 2, tig = lane & 3;
    int row = w * 16 + gid + ((r & 1) ? 8 : 0);
    int col = ks * 16 + tig * 2 + ((r & 2) ? 8 : 0);
    float w0 = gwhh[(g * 128 + row) * 128 + col];
    float w1 = gwhh[(g * 128 + row) * 128 + col + 1];
    float h0 = __bfloat162float(__float2bfloat16(w0));
    float h1 = __bfloat162float(__float2bfloat16(w1));
    g_wfragHi[idx] = packbf(h0, h1);
    g_wfragLo[idx] = packbf(w0 - h0, w1 - h1);
}

// ---------------- K0c: LSTM [wih|whh] -> fragments ----------------
__global__ void k_prep_lfrag(const float* __restrict__ lwih, const float* __restrict__ lwhh) {
    int idx = blockIdx.x * blockDim.x + threadIdx.x;
    if (idx >= 65536) return;
    int r = idx & 3, lane = (idx >> 2) & 31, ks = (idx >> 7) & 15;
    int w = (idx >> 11) & 7, g = idx >> 14;
    int gid = lane >> 2, tig = lane & 3;
    int m = g * 128 + w * 16 + gid + ((r & 1) ? 8 : 0);
    int col = ks * 16 + tig * 2 + ((r & 2) ? 8 : 0);
    float w0, w1;
    if (col < 128) { w0 = lwih[m * 128 + col]; w1 = lwih[m * 128 + col + 1]; }
    else           { w0 = lwhh[m * 128 + col - 128]; w1 = lwhh[m * 128 + col - 127]; }
    float h0 = __bfloat162float(__float2bfloat16(w0));
    float h1 = __bfloat162float(__float2bfloat16(w1));
    g_lfragHi[idx] = packbf(h0, h1);
    g_lfragLo[idx] = packbf(w0 - h0, w1 - h1);
}

// ---------------- K1: conv1 tap table ----------------
__global__ void k_build_t1(const float* __restrict__ obj_emb, const float* __restrict__ col_emb,
                           const float* __restrict__ st_emb, const float* __restrict__ w1) {
    int blk = blockIdx.x;
    int tap = blk / 132, combo = blk % 132;
    int ty = tap >> 1, tx = tap & 1;
    int s = combo & 1, q = combo >> 1;
    int cc = q % 6, o = q / 6;
    __shared__ __align__(16) float ev[48];
    int t = threadIdx.x;
    if (t < 16)       ev[t] = col_emb[cc * 16 + t];
    else if (t < 32)  ev[t] = obj_emb[o * 16 + (t - 16)];
    else if (t < 48)  ev[t] = st_emb[s * 16 + (t - 32)];
    __syncthreads();
    float v = 0.f;
    #pragma unroll 8
    for (int k = 0; k < 48; k++) v += w1[((t * 48 + k) * 2 + ty) * 2 + tx] * ev[k];
    g_T1[(tap * 132 + combo) * 64 + t] = v;
}

// ---------------- K2: GRU input proj table ----------------
__global__ void k_build_gi(const float* __restrict__ word_emb, const float* __restrict__ gwih,
                           const float* __restrict__ gbih, const float* __restrict__ gbhh) {
    int v = blockIdx.x, g = threadIdx.x;
    __shared__ __align__(16) float ev[32];
    if (g < 32) ev[g] = word_emb[v * 32 + g];
    __syncthreads();
    float a = gbih[g] + gbhh[g];
    const float* w = gwih + g * 32;
    #pragma unroll 8
    for (int k = 0; k < 32; k++) a += w[k] * ev[k];
    int gate = g >> 7, j = g & 127;
    g_GI2[v * 512 + j * 4 + gate] = a;
}

// ---------------- K3: conv stack (4 elems/block, 128 thr, register-batched) --
__global__ __launch_bounds__(128)
void k_conv(const int* __restrict__ image, const float* __restrict__ b1,
            const float* __restrict__ b2, const float* __restrict__ b3) {
    int t = threadIdx.x;
    int b0 = blockIdx.x * 4;
    __shared__ __align__(16) int   s_combo[4][49];
    __shared__ __align__(16) float s_c1[4][36 * 64];
    __shared__ __align__(16) float s_p[4][9 * 64];
    __shared__ __align__(16) float s_q[4][4 * 64];

    for (int i = t; i < 196; i += 128) {
        int e = i / 49, li = i % 49;
        const int* px = image + ((b0 + e) * 49 + li) * 3;
        s_combo[e][li] = (px[0] * 6 + px[1]) * 2 + px[2];
    }
    __syncthreads();
    // conv1 via tap table
    for (int idx = t; idx < 2304; idx += 128) {
        int c = idx & 63, pos = idx >> 6;
        int y = pos / 6, x = pos % 6;
        float bb = b1[c];
        #pragma unroll
        for (int e = 0; e < 4; e++) {
            float v = bb;
            v += g_T1[(0 * 132 + s_combo[e][y * 7 + x]) * 64 + c];
            v += g_T1[(1 * 132 + s_combo[e][y * 7 + x + 1]) * 64 + c];
            v += g_T1[(2 * 132 + s_combo[e][(y + 1) * 7 + x]) * 64 + c];
            v += g_T1[(3 * 132 + s_combo[e][(y + 1) * 7 + x + 1]) * 64 + c];
            s_c1[e][pos * 64 + c] = fmaxf(v, 0.f);
        }
    }
    __syncthreads();
    // maxpool
    for (int idx = t; idx < 576; idx += 128) {
        int c = idx & 63, pos = idx >> 6;
        int y = pos / 3, x = pos % 3;
        int p0 = (2 * y) * 6 + 2 * x;
        #pragma unroll
        for (int e = 0; e < 4; e++)
            s_p[e][pos * 64 + c] =
                fmaxf(fmaxf(s_c1[e][p0 * 64 + c], s_c1[e][(p0 + 1) * 64 + c]),
                      fmaxf(s_c1[e][(p0 + 6) * 64 + c], s_c1[e][(p0 + 7) * 64 + c]));
    }
    __syncthreads();
    // conv2: each thread 2 (c,pos), weights loaded once, 4 elems in regs
    for (int idx = t; idx < 256; idx += 128) {
        int c = idx & 63, pos = idx >> 6;
        int y = pos >> 1, x = pos & 1;
        int p00 = y * 3 + x;
        float v[4];
        float bb = b2[c];
        #pragma unroll
        for (int e = 0; e < 4; e++) v[e] = bb;
        #pragma unroll 4
        for (int ci = 0; ci < 64; ci++) {
            float4 w4 = *(const float4*)(g_w2T + ci * 256 + c * 4);
            #pragma unroll
            for (int e = 0; e < 4; e++)
                v[e] += w4.x * s_p[e][p00 * 64 + ci] + w4.y * s_p[e][(p00 + 1) * 64 + ci]
                      + w4.z * s_p[e][(p00 + 3) * 64 + ci] + w4.w * s_p[e][(p00 + 4) * 64 + ci];
        }
        #pragma unroll
        for (int e = 0; e < 4; e++) s_q[e][pos * 64 + c] = fmaxf(v[e], 0.f);
    }
    __syncthreads();
    // conv3: thread = out channel
    {
        float v[4];
        float bb = b3[t];
        #pragma unroll
        for (int e = 0; e < 4; e++) v[e] = bb;
        #pragma unroll 4
        for (int ci = 0; ci < 64; ci++) {
            float4 w4 = *(const float4*)(g_w3T + ci * 512 + t * 4);
            #pragma unroll
            for (int e = 0; e < 4; e++)
                v[e] += w4.x * s_q[e][0 * 64 + ci] + w4.y * s_q[e][1 * 64 + ci]
                      + w4.z * s_q[e][2 * 64 + ci] + w4.w * s_q[e][3 * 64 + ci];
        }
        #pragma unroll
        for (int e = 0; e < 4; e++) g_x[(b0 + e) * 128 + t] = fmaxf(v[e], 0.f);
    }
}

// ---------------- K4: mma.sync LSTM (64 batch/block, 256 thr) ----------------
// smem: BHI [64][132]u32 33792 | BLO 33792 = 67584
static constexpr int LS_SZ = 67584;

__global__ __launch_bounds__(256)
void k_lstm_mma(const float* __restrict__ memory, const float* __restrict__ bih,
                const float* __restrict__ bhh, float* __restrict__ mem_out) {
    extern __shared__ __align__(16) char smem[];
    uint32_t* bhi = (uint32_t*)smem;
    uint32_t* blo = bhi + 64 * 132;
    int tid = threadIdx.x;
    int w = tid >> 5, lane = tid & 31;
    int gid = lane >> 2, tig = lane & 3;
    int b0 = blockIdx.x * 64;

    // stage B = [x | h] split bf16
    for (int i = tid; i < 8192; i += 256) {
        int n = i >> 7, kp = i & 127;
        int k = kp * 2;
        float2 v = (k < 128) ? *(const float2*)(g_x + (b0 + n) * 128 + k)
                             : *(const float2*)(memory + (b0 + n) * 256 + (k - 128));
        float h0 = __bfloat162float(__float2bfloat16(v.x));
        float h1 = __bfloat162float(__float2bfloat16(v.y));
        bhi[n * 132 + kp] = packbf(h0, h1);
        blo[n * 132 + kp] = packbf(v.x - h0, v.y - h1);
    }
    int j0 = w * 16 + gid;
    float bb[4][2];
    #pragma unroll
    for (int g = 0; g < 4; g++) {
        bb[g][0] = bih[g * 128 + j0] + bhh[g * 128 + j0];
        bb[g][1] = bih[g * 128 + j0 + 8] + bhh[g * 128 + j0 + 8];
    }
    __syncthreads();

    #pragma unroll
    for (int half = 0; half < 2; half++) {
        float D[4][4][4];
        #pragma unroll
        for (int g = 0; g < 4; g++)
            #pragma unroll
            for (int nt = 0; nt < 4; nt++)
                #pragma unroll
                for (int r = 0; r < 4; r++) D[g][nt][r] = 0.f;

        #pragma unroll
        for (int ks = 0; ks < 16; ks++) {
            uint32_t B0h[4], B1h[4], B0l[4], B1l[4];
            #pragma unroll
            for (int nt = 0; nt < 4; nt++) {
                int n = (half * 4 + nt) * 8 + gid;
                int kp = ks * 8 + tig;
                B0h[nt] = bhi[n * 132 + kp]; B1h[nt] = bhi[n * 132 + kp + 4];
                B0l[nt] = blo[n * 132 + kp]; B1l[nt] = blo[n * 132 + kp + 4];
            }
            #pragma unroll
            for (int g = 0; g < 4; g++) {
                uint32_t Ah[4], Al[4];
                uint32_t foff = (((uint32_t)(g * 8 + w) * 16 + ks) << 7) + lane * 4;
                *(uint4*)Ah = *(const uint4*)(g_lfragHi + foff);
                *(uint4*)Al = *(const uint4*)(g_lfragLo + foff);
                #pragma unroll
                for (int nt = 0; nt < 4; nt++) {
                    mma_bf16(D[g][nt], Ah, B0h[nt], B1h[nt]);
                    mma_bf16(D[g][nt], Ah, B0l[nt], B1l[nt]);
                    mma_bf16(D[g][nt], Al, B0h[nt], B1h[nt]);
                }
            }
        }
        #pragma unroll
        for (int nt = 0; nt < 4; nt++) {
            #pragma unroll
            for (int c = 0; c < 2; c++) {
                int n = (half * 4 + nt) * 8 + tig * 2 + c;
                #pragma unroll
                for (int jj = 0; jj < 2; jj++) {
                    int j = j0 + jj * 8;
                    int reg = jj * 2 + c;
                    float gi_ = bb[0][jj] + D[0][nt][reg];
                    float gf  = bb[1][jj] + D[1][nt][reg];
                    float gg  = bb[2][jj] + D[2][nt][reg];
                    float go  = bb[3][jj] + D[3][nt][reg];
                    float c_in = memory[(b0 + n) * 256 + 128 + j];
                    float cn = sigm_(gf) * c_in + sigm_(gi_) * tanh_(gg);
                    float hn = sigm_(go) * tanh_(cn);
                    mem_out[(b0 + n) * 256 + j] = hn;
                    mem_out[(b0 + n) * 256 + 128 + j] = cn;
                }
            }
        }
    }
}

// ---------------- K5: mma.sync GRU (64 batch/block, 256 thr) ----------------
static constexpr int GQ_WHI = 0;
static constexpr int GQ_WLO = 98304;
static constexpr int GQ_BHI = 196608;
static constexpr int GQ_BLO = 196608 + 17408;
static constexpr int GQ_SZ  = 196608 + 34816;

__global__ __launch_bounds__(256, 1)
void k_gru_mma(const int* __restrict__ text) {
    extern __shared__ __align__(16) char smem[];
    int tid = threadIdx.x;
    int w = tid >> 5, lane = tid & 31;
    int gid = lane >> 2, tig = lane & 3;
    int b0 = blockIdx.x * 64;

    {
        const uint4* s1 = (const uint4*)g_wfragHi;
        const uint4* s2 = (const uint4*)g_wfragLo;
        uint4* d1 = (uint4*)(smem + GQ_WHI);
        uint4* d2 = (uint4*)(smem + GQ_WLO);
        for (int i = tid; i < 6144; i += 256) { d1[i] = s1[i]; d2[i] = s2[i]; }
        uint4 z = make_uint4(0, 0, 0, 0);
        uint4* dz = (uint4*)(smem + GQ_BHI);
        for (int i = tid; i < 2176; i += 256) dz[i] = z;
    }
    __syncthreads();

    const uint32_t* bhi = (const uint32_t*)(smem + GQ_BHI);
    const uint32_t* blo = (const uint32_t*)(smem + GQ_BLO);

    for (int tt = 0; tt < 20; tt++) {
        float D[3][8][4];
        #pragma unroll
        for (int g = 0; g < 3; g++)
            #pragma unroll
            for (int nt = 0; nt < 8; nt++)
                #pragma unroll
                for (int r = 0; r < 4; r++) D[g][nt][r] = 0.f;

        #pragma unroll
        for (int ks = 0; ks < 8; ks++) {
            uint32_t B0h[8], B1h[8], B0l[8], B1l[8];
            #pragma unroll
            for (int nt = 0; nt < 8; nt++) {
                int n = nt * 8 + gid;
                int kp = ks * 8 + tig;
                B0h[nt] = bhi[n * 68 + kp];  B1h[nt] = bhi[n * 68 + kp + 4];
                B0l[nt] = blo[n * 68 + kp];  B1l[nt] = blo[n * 68 + kp + 4];
            }
            #pragma unroll
            for (int g = 0; g < 3; g++) {
                uint32_t Ah[4], Al[4];
                uint32_t foff = (((uint32_t)(g * 8 + w) * 8 + ks) << 9) + lane * 16;
                *(uint4*)Ah = *(const uint4*)(smem + GQ_WHI + foff);
                *(uint4*)Al = *(const uint4*)(smem + GQ_WLO + foff);
                #pragma unroll
                for (int nt = 0; nt < 8; nt++) {
                    mma_bf16(D[g][nt], Ah, B0h[nt], B1h[nt]);
                    mma_bf16(D[g][nt], Ah, B0l[nt], B1l[nt]);
                    mma_bf16(D[g][nt], Al, B0h[nt], B1h[nt]);
                }
            }
        }
        __syncthreads();

        #pragma unroll
        for (int nt = 0; nt < 8; nt++) {
            #pragma unroll
            for (int c = 0; c < 2; c++) {
                int n = nt * 8 + tig * 2 + c;
                int word = text[(b0 + n) * 20 + tt];
                const float4* gi4 = (const float4*)(g_GI2 + word * 512);
                #pragma unroll
                for (int jj = 0; jj < 2; jj++) {
                    int j = w * 16 + gid + jj * 8;
                    int reg = jj * 2 + c;
                    float4 gv = gi4[j];
                    uint32_t boff = (uint32_t)(n * 68 + (j >> 1)) * 4 + (uint32_t)(j & 1) * 2;
                    float hp = __bfloat162float(*(__nv_bfloat16*)(smem + GQ_BHI + boff))
                             + __bfloat162float(*(__nv_bfloat16*)(smem + GQ_BLO + boff));
                    float r = sigm_(gv.x + D[0][nt][reg]);
                    float z = sigm_(gv.y + D[1][nt][reg]);
                    float nv = tanh_(gv.z + r * D[2][nt][reg]);
                    float h = (1.f - z) * nv + z * hp;
                    __nv_bfloat16 hhi = __float2bfloat16(h);
                    *(__nv_bfloat16*)(smem + GQ_BHI + boff) = hhi;
                    *(__nv_bfloat16*)(smem + GQ_BLO + boff) =
                        __float2bfloat16(h - __bfloat162float(hhi));
                    if (tt == 19) g_ht[(b0 + n) * 128 + j] = h;
                }
            }
        }
        __syncthreads();
    }
}

// ---------------- K6: heads (16 batch/block) ----------------
__global__ __launch_bounds__(256)
void k_heads(const float* __restrict__ mem, const float* __restrict__ ab1,
             const float* __restrict__ aw2, const float* __restrict__ ab2,
             const float* __restrict__ cb1, const float* __restrict__ cw2,
             const float* __restrict__ cb2, float* __restrict__ lp, float* __restrict__ value) {
    int tid = threadIdx.x;
    int b0 = blockIdx.x * 16;
    __shared__ __align__(16) float s_emb[16 * 256];
    __shared__ __align__(16) float s_a1[16 * 256];
    __shared__ __align__(16) float s_logits[16 * 8];

    for (int idx = tid; idx < 16 * 128; idx += 256) {
        int bi = idx >> 7, k = idx & 127;
        s_emb[bi * 256 + k]       = mem[(b0 + bi) * 256 + k];
        s_emb[bi * 256 + 128 + k] = g_ht[(b0 + bi) * 128 + k];
    }
    __syncthreads();
    {
        float acc[16];
        float bb = ab1[tid];
        #pragma unroll
        for (int bi = 0; bi < 16; bi++) acc[bi] = bb;
        for (int k = 0; k < 256; k += 4) {
            float4 w4 = *(const float4*)(g_aw1T + (k >> 2) * 1024 + tid * 4);
            #pragma unroll
            for (int bi = 0; bi < 16; bi++) {
                float4 e = *(const float4*)(s_emb + bi * 256 + k);
                acc[bi] += w4.x*e.x + w4.y*e.y + w4.z*e.z + w4.w*e.w;
            }
        }
        #pragma unroll
        for (int bi = 0; bi < 16; bi++) s_a1[bi * 256 + tid] = tanh_(acc[bi]);
    }
    __syncthreads();
    int warp = tid >> 5, lane = tid & 31;
    for (int bi = warp * 2; bi < warp * 2 + 2; bi++)
        for (int a = 0; a < 7; a++) {
            float s = 0.f;
            for (int k = lane; k < 256; k += 32) s += aw2[a * 256 + k] * s_a1[bi * 256 + k];
            #pragma unroll
            for (int off = 16; off; off >>= 1) s += __shfl_xor_sync(0xffffffffu, s, off);
            if (lane == 0) s_logits[bi * 8 + a] = s + ab2[a];
        }
    __syncthreads();
    {
        float acc[16];
        float bb = cb1[tid];
        #pragma unroll
        for (int bi = 0; bi < 16; bi++) acc[bi] = bb;
        for (int k = 0; k < 256; k += 4) {
            float4 w4 = *(const float4*)(g_cw1T + (k >> 2) * 1024 + tid * 4);
            #pragma unroll
            for (int bi = 0; bi < 16; bi++) {
                float4 e = *(const float4*)(s_emb + bi * 256 + k);
                acc[bi] += w4.x*e.x + w4.y*e.y + w4.z*e.z + w4.w*e.w;
            }
        }
        #pragma unroll
        for (int bi = 0; bi < 16; bi++) s_a1[bi * 256 + tid] = tanh_(acc[bi]);
    }
    if (tid < 16) {
        float m = -1e30f;
        #pragma unroll
        for (int a = 0; a < 7; a++) m = fmaxf(m, s_logits[tid * 8 + a]);
        float sum = 0.f;
        #pragma unroll
        for (int a = 0; a < 7; a++) sum += expf(s_logits[tid * 8 + a] - m);
        float lse = m + logf(sum);
        #pragma unroll
        for (int a = 0; a < 7; a++) lp[(b0 + tid) * 7 + a] = s_logits[tid * 8 + a] - lse;
    }
    __syncthreads();
    for (int bi = warp * 2; bi < warp * 2 + 2; bi++) {
        float s = 0.f;
        for (int k = lane; k < 256; k += 32) s += cw2[k] * s_a1[bi * 256 + k];
        #pragma unroll
        for (int off = 16; off; off >>= 1) s += __shfl_xor_sync(0xffffffffu, s, off);
        if (lane == 0) value[b0 + bi] = s + cb2[0];
    }
}

// ---------------- launch ----------------
extern "C" void kernel_launch(void* const* d_in, const int* in_sizes, int n_in,
                              void* d_out, int out_size) {
    const int*   image  = (const int*)  d_in[0];
    const float* memory = (const float*)d_in[1];
    const int*   text   = (const int*)  d_in[2];
    const float* obj_e  = (const float*)d_in[3];
    const float* col_e  = (const float*)d_in[4];
    const float* st_e   = (const float*)d_in[5];
    const float* c1w    = (const float*)d_in[6];
    const float* c1b    = (const float*)d_in[7];
    const float* c2w    = (const float*)d_in[8];
    const float* c2b    = (const float*)d_in[9];
    const float* c3w    = (const float*)d_in[10];
    const float* c3b    = (const float*)d_in[11];
    const float* lwih   = (const float*)d_in[12];
    const float* lwhh   = (const float*)d_in[13];
    const float* lbih   = (const float*)d_in[14];
    const float* lbhh   = (const float*)d_in[15];
    const float* wemb   = (const float*)d_in[16];
    const float* gwih   = (const float*)d_in[17];
    const float* gwhh   = (const float*)d_in[18];
    const float* gbih   = (const float*)d_in[19];
    const float* gbhh   = (const float*)d_in[20];
    const float* aw1    = (const float*)d_in[21];
    const float* ab1    = (const float*)d_in[22];
    const float* aw2    = (const float*)d_in[23];
    const float* ab2    = (const float*)d_in[24];
    const float* cw1    = (const float*)d_in[25];
    const float* cb1    = (const float*)d_in[26];
    const float* cw2    = (const float*)d_in[27];
    const float* cb2    = (const float*)d_in[28];

    const int B = in_sizes[1] / 256;
    float* out   = (float*)d_out;
    float* lp    = out;
    float* value = out + (size_t)B * 7;
    float* memo  = out + (size_t)B * 8;

    cudaFuncSetAttribute(k_gru_mma, cudaFuncAttributeMaxDynamicSharedMemorySize, GQ_SZ);
    cudaFuncSetAttribute(k_lstm_mma, cudaFuncAttributeMaxDynamicSharedMemorySize, LS_SZ);

    dim3 pgrid(64, 4);
    k_prep<<<pgrid, 256>>>(aw1, cw1, c2w, c3w);
    k_prep_frag<<<96, 256>>>(gwhh);
    k_prep_lfrag<<<256, 256>>>(lwih, lwhh);
    k_build_t1<<<4 * 132, 64>>>(obj_e, col_e, st_e, c1w);
    k_build_gi<<<100, 384>>>(wemb, gwih, gbih, gbhh);

    k_conv<<<B / 4, 128>>>(image, c1b, c2b, c3b);
    k_lstm_mma<<<B / 64, 256, LS_SZ>>>(memory, lbih, lbhh, memo);
    k_gru_mma<<<B / 64, 256, GQ_SZ>>>(text);
    k_heads<<<B / 16, 256>>>(memo, ab1, aw2, ab2, cb1, cw2, cb2, lp, value);
}

// round 12
// speedup vs baseline: 1.6245x; 1.0975x over previous
#include <cuda_runtime.h>
#include <cuda_bf16.h>
#include <cstdint>

// ---------------- scratch ----------------
__device__ __align__(16) float g_T1[4 * 132 * 64];
__device__ __align__(16) float g_GI2[100 * 512];   // [word][j][4]={r,z,n,pad}, bhh baked
__device__ __align__(16) float g_ht[8192 * 128];
__device__ __align__(16) float g_x[8192 * 128];
__device__ __align__(16) float g_w2T[64 * 256];
__device__ __align__(16) float g_w3T[128 * 256];
// GRU whh mma fragments: [g3][w8][ks8][lane32][4] bf16x2
__device__ __align__(16) uint32_t g_wfragHi[3 * 8 * 8 * 32 * 4];
__device__ __align__(16) uint32_t g_wfragLo[3 * 8 * 8 * 32 * 4];
// LSTM [wih|whh] mma fragments: [g4][w8][ks16][lane32][4] bf16x2
__device__ __align__(16) uint32_t g_lfragHi[4 * 8 * 16 * 32 * 4];
__device__ __align__(16) uint32_t g_lfragLo[4 * 8 * 16 * 32 * 4];
// Heads [aw1;cw1] mma fragments: same shape as LSTM
__device__ __align__(16) uint32_t g_hfragHi[4 * 8 * 16 * 32 * 4];
__device__ __align__(16) uint32_t g_hfragLo[4 * 8 * 16 * 32 * 4];

__device__ __forceinline__ float sigm_(float x) { return 1.0f / (1.0f + __expf(-x)); }
__device__ __forceinline__ float tanh_(float x) { return 2.0f / (1.0f + __expf(-2.0f * x)) - 1.0f; }

__device__ __forceinline__ void mma_bf16(float* d, const uint32_t* a, uint32_t b0, uint32_t b1) {
    asm volatile("mma.sync.aligned.m16n8k16.row.col.f32.bf16.bf16.f32 "
        "{%0,%1,%2,%3}, {%4,%5,%6,%7}, {%8,%9}, {%0,%1,%2,%3};"
        : "+f"(d[0]), "+f"(d[1]), "+f"(d[2]), "+f"(d[3])
        : "r"(a[0]), "r"(a[1]), "r"(a[2]), "r"(a[3]), "r"(b0), "r"(b1));
}
__device__ __forceinline__ uint32_t packbf(float a, float b) {
    __nv_bfloat16 ha = __float2bfloat16(a), hb = __float2bfloat16(b);
    return (uint32_t)*(uint16_t*)&ha | ((uint32_t)*(uint16_t*)&hb << 16);
}

// ---------------- K0: transpose prep (conv weights) ----------------
__global__ void k_prep(const float* __restrict__ c2w, const float* __restrict__ c3w) {
    int m = blockIdx.y;
    const float* src; float* dst; int N, K;
    if (m == 0) { src = c2w; dst = g_w2T; N = 64;  K = 256; }
    else        { src = c3w; dst = g_w3T; N = 128; K = 256; }
    int total = N * K;
    for (int idx = blockIdx.x * blockDim.x + threadIdx.x; idx < total;
         idx += gridDim.x * blockDim.x) {
        int j = idx / K, k = idx % K;
        dst[(k >> 2) * (N * 4) + j * 4 + (k & 3)] = src[idx];
    }
}

// ---------------- K0b: GRU whh -> fragments ----------------
__global__ void k_prep_frag(const float* __restrict__ gwhh) {
    int idx = blockIdx.x * blockDim.x + threadIdx.x;
    if (idx >= 24576) return;
    int r = idx & 3, lane = (idx >> 2) & 31, ks = (idx >> 7) & 7;
    int w = (idx >> 10) & 7, g = idx >> 13;
    int gid = lane >> 2, tig = lane & 3;
    int row = w * 16 + gid + ((r & 1) ? 8 : 0);
    int col = ks * 16 + tig * 2 + ((r & 2) ? 8 : 0);
    float w0 = gwhh[(g * 128 + row) * 128 + col];
    float w1 = gwhh[(g * 128 + row) * 128 + col + 1];
    float h0 = __bfloat162float(__float2bfloat16(w0));
    float h1 = __bfloat162float(__float2bfloat16(w1));
    g_wfragHi[idx] = packbf(h0, h1);
    g_wfragLo[idx] = packbf(w0 - h0, w1 - h1);
}

// ---------------- K0c: 512x256 stacked matrices -> fragments ----------------
// mode 0: LSTM [wih|whh] concat on K; mode 1: heads [aw1;cw1] stacked on M
__global__ void k_prep_frag512(const float* __restrict__ A, const float* __restrict__ B,
                               uint32_t* __restrict__ dHi, uint32_t* __restrict__ dLo,
                               int mode) {
    int idx = blockIdx.x * blockDim.x + threadIdx.x;
    if (idx >= 65536) return;
    int r = idx & 3, lane = (idx >> 2) & 31, ks = (idx >> 7) & 15;
    int w = (idx >> 11) & 7, g = idx >> 14;
    int gid = lane >> 2, tig = lane & 3;
    int m = g * 128 + w * 16 + gid + ((r & 1) ? 8 : 0);
    int col = ks * 16 + tig * 2 + ((r & 2) ? 8 : 0);
    float w0, w1;
    if (mode == 0) {
        if (col < 128) { w0 = A[m * 128 + col];       w1 = A[m * 128 + col + 1]; }
        else           { w0 = B[m * 128 + col - 128]; w1 = B[m * 128 + col - 127]; }
    } else {
        if (m < 256) { w0 = A[m * 256 + col];         w1 = A[m * 256 + col + 1]; }
        else         { w0 = B[(m - 256) * 256 + col]; w1 = B[(m - 256) * 256 + col + 1]; }
    }
    float h0 = __bfloat162float(__float2bfloat16(w0));
    float h1 = __bfloat162float(__float2bfloat16(w1));
    dHi[idx] = packbf(h0, h1);
    dLo[idx] = packbf(w0 - h0, w1 - h1);
}

// ---------------- K1: conv1 tap table ----------------
__global__ void k_build_t1(const float* __restrict__ obj_emb, const float* __restrict__ col_emb,
                           const float* __restrict__ st_emb, const float* __restrict__ w1) {
    int blk = blockIdx.x;
    int tap = blk / 132, combo = blk % 132;
    int ty = tap >> 1, tx = tap & 1;
    int s = combo & 1, q = combo >> 1;
    int cc = q % 6, o = q / 6;
    __shared__ __align__(16) float ev[48];
    int t = threadIdx.x;
    if (t < 16)       ev[t] = col_emb[cc * 16 + t];
    else if (t < 32)  ev[t] = obj_emb[o * 16 + (t - 16)];
    else if (t < 48)  ev[t] = st_emb[s * 16 + (t - 32)];
    __syncthreads();
    float v = 0.f;
    #pragma unroll 8
    for (int k = 0; k < 48; k++) v += w1[((t * 48 + k) * 2 + ty) * 2 + tx] * ev[k];
    g_T1[(tap * 132 + combo) * 64 + t] = v;
}

// ---------------- K2: GRU input proj table ----------------
__global__ void k_build_gi(const float* __restrict__ word_emb, const float* __restrict__ gwih,
                           const float* __restrict__ gbih, const float* __restrict__ gbhh) {
    int v = blockIdx.x, g = threadIdx.x;
    __shared__ __align__(16) float ev[32];
    if (g < 32) ev[g] = word_emb[v * 32 + g];
    __syncthreads();
    float a = gbih[g] + gbhh[g];
    const float* w = gwih + g * 32;
    #pragma unroll 8
    for (int k = 0; k < 32; k++) a += w[k] * ev[k];
    int gate = g >> 7, j = g & 127;
    g_GI2[v * 512 + j * 4 + gate] = a;
}

// ---------------- K3: conv stack (4 elems/block, 128 thr) ----------------
__global__ __launch_bounds__(128)
void k_conv(const int* __restrict__ image, const float* __restrict__ b1,
            const float* __restrict__ b2, const float* __restrict__ b3) {
    int t = threadIdx.x;
    int b0 = blockIdx.x * 4;
    __shared__ __align__(16) int   s_combo[4][49];
    __shared__ __align__(16) float s_c1[4][36 * 64];
    __shared__ __align__(16) float s_p[4][9 * 64];
    __shared__ __align__(16) float s_q[4][4 * 64];

    for (int i = t; i < 196; i += 128) {
        int e = i / 49, li = i % 49;
        const int* px = image + ((b0 + e) * 49 + li) * 3;
        s_combo[e][li] = (px[0] * 6 + px[1]) * 2 + px[2];
    }
    __syncthreads();
    for (int idx = t; idx < 2304; idx += 128) {
        int c = idx & 63, pos = idx >> 6;
        int y = pos / 6, x = pos % 6;
        float bb = b1[c];
        #pragma unroll
        for (int e = 0; e < 4; e++) {
            float v = bb;
            v += g_T1[(0 * 132 + s_combo[e][y * 7 + x]) * 64 + c];
            v += g_T1[(1 * 132 + s_combo[e][y * 7 + x + 1]) * 64 + c];
            v += g_T1[(2 * 132 + s_combo[e][(y + 1) * 7 + x]) * 64 + c];
            v += g_T1[(3 * 132 + s_combo[e][(y + 1) * 7 + x + 1]) * 64 + c];
            s_c1[e][pos * 64 + c] = fmaxf(v, 0.f);
        }
    }
    __syncthreads();
    for (int idx = t; idx < 576; idx += 128) {
        int c = idx & 63, pos = idx >> 6;
        int y = pos / 3, x = pos % 3;
        int p0 = (2 * y) * 6 + 2 * x;
        #pragma unroll
        for (int e = 0; e < 4; e++)
            s_p[e][pos * 64 + c] =
                fmaxf(fmaxf(s_c1[e][p0 * 64 + c], s_c1[e][(p0 + 1) * 64 + c]),
                      fmaxf(s_c1[e][(p0 + 6) * 64 + c], s_c1[e][(p0 + 7) * 64 + c]));
    }
    __syncthreads();
    for (int idx = t; idx < 256; idx += 128) {
        int c = idx & 63, pos = idx >> 6;
        int y = pos >> 1, x = pos & 1;
        int p00 = y * 3 + x;
        float v[4];
        float bb = b2[c];
        #pragma unroll
        for (int e = 0; e < 4; e++) v[e] = bb;
        #pragma unroll 4
        for (int ci = 0; ci < 64; ci++) {
            float4 w4 = *(const float4*)(g_w2T + ci * 256 + c * 4);
            #pragma unroll
            for (int e = 0; e < 4; e++)
                v[e] += w4.x * s_p[e][p00 * 64 + ci] + w4.y * s_p[e][(p00 + 1) * 64 + ci]
                      + w4.z * s_p[e][(p00 + 3) * 64 + ci] + w4.w * s_p[e][(p00 + 4) * 64 + ci];
        }
        #pragma unroll
        for (int e = 0; e < 4; e++) s_q[e][pos * 64 + c] = fmaxf(v[e], 0.f);
    }
    __syncthreads();
    {
        float v[4];
        float bb = b3[t];
        #pragma unroll
        for (int e = 0; e < 4; e++) v[e] = bb;
        #pragma unroll 4
        for (int ci = 0; ci < 64; ci++) {
            float4 w4 = *(const float4*)(g_w3T + ci * 512 + t * 4);
            #pragma unroll
            for (int e = 0; e < 4; e++)
                v[e] += w4.x * s_q[e][0 * 64 + ci] + w4.y * s_q[e][1 * 64 + ci]
                      + w4.z * s_q[e][2 * 64 + ci] + w4.w * s_q[e][3 * 64 + ci];
        }
        #pragma unroll
        for (int e = 0; e < 4; e++) g_x[(b0 + e) * 128 + t] = fmaxf(v[e], 0.f);
    }
}

// ---------------- K4: mma.sync LSTM (64 batch/block, 256 thr) ----------------
static constexpr int LS_SZ = 67584;

__global__ __launch_bounds__(256)
void k_lstm_mma(const float* __restrict__ memory, const float* __restrict__ bih,
                const float* __restrict__ bhh, float* __restrict__ mem_out) {
    extern __shared__ __align__(16) char smem[];
    uint32_t* bhi = (uint32_t*)smem;
    uint32_t* blo = bhi + 64 * 132;
    int tid = threadIdx.x;
    int w = tid >> 5, lane = tid & 31;
    int gid = lane >> 2, tig = lane & 3;
    int b0 = blockIdx.x * 64;

    for (int i = tid; i < 8192; i += 256) {
        int n = i >> 7, kp = i & 127;
        int k = kp * 2;
        float2 v = (k < 128) ? *(const float2*)(g_x + (b0 + n) * 128 + k)
                             : *(const float2*)(memory + (b0 + n) * 256 + (k - 128));
        float h0 = __bfloat162float(__float2bfloat16(v.x));
        float h1 = __bfloat162float(__float2bfloat16(v.y));
        bhi[n * 132 + kp] = packbf(h0, h1);
        blo[n * 132 + kp] = packbf(v.x - h0, v.y - h1);
    }
    int j0 = w * 16 + gid;
    float bb[4][2];
    #pragma unroll
    for (int g = 0; g < 4; g++) {
        bb[g][0] = bih[g * 128 + j0] + bhh[g * 128 + j0];
        bb[g][1] = bih[g * 128 + j0 + 8] + bhh[g * 128 + j0 + 8];
    }
    __syncthreads();

    #pragma unroll
    for (int half = 0; half < 2; half++) {
        float D[4][4][4];
        #pragma unroll
        for (int g = 0; g < 4; g++)
            #pragma unroll
            for (int nt = 0; nt < 4; nt++)
                #pragma unroll
                for (int r = 0; r < 4; r++) D[g][nt][r] = 0.f;

        #pragma unroll
        for (int ks = 0; ks < 16; ks++) {
            uint32_t B0h[4], B1h[4], B0l[4], B1l[4];
            #pragma unroll
            for (int nt = 0; nt < 4; nt++) {
                int n = (half * 4 + nt) * 8 + gid;
                int kp = ks * 8 + tig;
                B0h[nt] = bhi[n * 132 + kp]; B1h[nt] = bhi[n * 132 + kp + 4];
                B0l[nt] = blo[n * 132 + kp]; B1l[nt] = blo[n * 132 + kp + 4];
            }
            #pragma unroll
            for (int g = 0; g < 4; g++) {
                uint32_t Ah[4], Al[4];
                uint32_t foff = (((uint32_t)(g * 8 + w) * 16 + ks) << 7) + lane * 4;
                *(uint4*)Ah = *(const uint4*)(g_lfragHi + foff);
                *(uint4*)Al = *(const uint4*)(g_lfragLo + foff);
                #pragma unroll
                for (int nt = 0; nt < 4; nt++) {
                    mma_bf16(D[g][nt], Ah, B0h[nt], B1h[nt]);
                    mma_bf16(D[g][nt], Ah, B0l[nt], B1l[nt]);
                    mma_bf16(D[g][nt], Al, B0h[nt], B1h[nt]);
                }
            }
        }
        #pragma unroll
        for (int nt = 0; nt < 4; nt++) {
            #pragma unroll
            for (int c = 0; c < 2; c++) {
                int n = (half * 4 + nt) * 8 + tig * 2 + c;
                #pragma unroll
                for (int jj = 0; jj < 2; jj++) {
                    int j = j0 + jj * 8;
                    int reg = jj * 2 + c;
                    float gi_ = bb[0][jj] + D[0][nt][reg];
                    float gf  = bb[1][jj] + D[1][nt][reg];
                    float gg  = bb[2][jj] + D[2][nt][reg];
                    float go  = bb[3][jj] + D[3][nt][reg];
                    float c_in = memory[(b0 + n) * 256 + 128 + j];
                    float cn = sigm_(gf) * c_in + sigm_(gi_) * tanh_(gg);
                    float hn = sigm_(go) * tanh_(cn);
                    mem_out[(b0 + n) * 256 + j] = hn;
                    mem_out[(b0 + n) * 256 + 128 + j] = cn;
                }
            }
        }
    }
}

// ---------------- K5: mma.sync GRU (64 batch/block, 256 thr) ----------------
static constexpr int GQ_WHI = 0;
static constexpr int GQ_WLO = 98304;
static constexpr int GQ_BHI = 196608;
static constexpr int GQ_BLO = 196608 + 17408;
static constexpr int GQ_SZ  = 196608 + 34816;

__global__ __launch_bounds__(256, 1)
void k_gru_mma(const int* __restrict__ text) {
    extern __shared__ __align__(16) char smem[];
    int tid = threadIdx.x;
    int w = tid >> 5, lane = tid & 31;
    int gid = lane >> 2, tig = lane & 3;
    int b0 = blockIdx.x * 64;

    {
        const uint4* s1 = (const uint4*)g_wfragHi;
        const uint4* s2 = (const uint4*)g_wfragLo;
        uint4* d1 = (uint4*)(smem + GQ_WHI);
        uint4* d2 = (uint4*)(smem + GQ_WLO);
        for (int i = tid; i < 6144; i += 256) { d1[i] = s1[i]; d2[i] = s2[i]; }
        uint4 z = make_uint4(0, 0, 0, 0);
        uint4* dz = (uint4*)(smem + GQ_BHI);
        for (int i = tid; i < 2176; i += 256) dz[i] = z;
    }
    __syncthreads();

    const uint32_t* bhi = (const uint32_t*)(smem + GQ_BHI);
    const uint32_t* blo = (const uint32_t*)(smem + GQ_BLO);

    for (int tt = 0; tt < 20; tt++) {
        float D[3][8][4];
        #pragma unroll
        for (int g = 0; g < 3; g++)
            #pragma unroll
            for (int nt = 0; nt < 8; nt++)
                #pragma unroll
                for (int r = 0; r < 4; r++) D[g][nt][r] = 0.f;

        #pragma unroll
        for (int ks = 0; ks < 8; ks++) {
            uint32_t B0h[8], B1h[8], B0l[8], B1l[8];
            #pragma unroll
            for (int nt = 0; nt < 8; nt++) {
                int n = nt * 8 + gid;
                int kp = ks * 8 + tig;
                B0h[nt] = bhi[n * 68 + kp];  B1h[nt] = bhi[n * 68 + kp + 4];
                B0l[nt] = blo[n * 68 + kp];  B1l[nt] = blo[n * 68 + kp + 4];
            }
            #pragma unroll
            for (int g = 0; g < 3; g++) {
                uint32_t Ah[4], Al[4];
                uint32_t foff = (((uint32_t)(g * 8 + w) * 8 + ks) << 9) + lane * 16;
                *(uint4*)Ah = *(const uint4*)(smem + GQ_WHI + foff);
                *(uint4*)Al = *(const uint4*)(smem + GQ_WLO + foff);
                #pragma unroll
                for (int nt = 0; nt < 8; nt++) {
                    mma_bf16(D[g][nt], Ah, B0h[nt], B1h[nt]);
                    mma_bf16(D[g][nt], Ah, B0l[nt], B1l[nt]);
                    mma_bf16(D[g][nt], Al, B0h[nt], B1h[nt]);
                }
            }
        }
        __syncthreads();

        #pragma unroll
        for (int nt = 0; nt < 8; nt++) {
            #pragma unroll
            for (int c = 0; c < 2; c++) {
                int n = nt * 8 + tig * 2 + c;
                int word = text[(b0 + n) * 20 + tt];
                const float4* gi4 = (const float4*)(g_GI2 + word * 512);
                #pragma unroll
                for (int jj = 0; jj < 2; jj++) {
                    int j = w * 16 + gid + jj * 8;
                    int reg = jj * 2 + c;
                    float4 gv = gi4[j];
                    uint32_t boff = (uint32_t)(n * 68 + (j >> 1)) * 4 + (uint32_t)(j & 1) * 2;
                    float hp = __bfloat162float(*(__nv_bfloat16*)(smem + GQ_BHI + boff))
                             + __bfloat162float(*(__nv_bfloat16*)(smem + GQ_BLO + boff));
                    float r = sigm_(gv.x + D[0][nt][reg]);
                    float z = sigm_(gv.y + D[1][nt][reg]);
                    float nv = tanh_(gv.z + r * D[2][nt][reg]);
                    float h = (1.f - z) * nv + z * hp;
                    __nv_bfloat16 hhi = __float2bfloat16(h);
                    *(__nv_bfloat16*)(smem + GQ_BHI + boff) = hhi;
                    *(__nv_bfloat16*)(smem + GQ_BLO + boff) =
                        __float2bfloat16(h - __bfloat162float(hhi));
                    if (tt == 19) g_ht[(b0 + n) * 128 + j] = h;
                }
            }
        }
        __syncthreads();
    }
}

// ---------------- K6: mma.sync heads (64 batch/block, 256 thr) ----------------
// smem: BHI [64][132]u32 33792 | BLO 33792 | A1A [64][264]f32 67584 | A1C 67584 | LOG 2048
static constexpr int HS_BHI = 0;
static constexpr int HS_BLO = 33792;
static constexpr int HS_A1A = 67584;
static constexpr int HS_A1C = 135168;
static constexpr int HS_LOG = 202752;
static constexpr int HS_SZ  = 204800;

__global__ __launch_bounds__(256, 1)
void k_heads_mma(const float* __restrict__ mem,
                 const float* __restrict__ ab1, const float* __restrict__ aw2,
                 const float* __restrict__ ab2, const float* __restrict__ cb1,
                 const float* __restrict__ cw2, const float* __restrict__ cb2,
                 float* __restrict__ lp, float* __restrict__ value) {
    extern __shared__ __align__(16) char smem[];
    uint32_t* bhi = (uint32_t*)(smem + HS_BHI);
    uint32_t* blo = (uint32_t*)(smem + HS_BLO);
    float* a1a = (float*)(smem + HS_A1A);
    float* a1c = (float*)(smem + HS_A1C);
    float* slog = (float*)(smem + HS_LOG);
    int tid = threadIdx.x;
    int w = tid >> 5, lane = tid & 31;
    int gid = lane >> 2, tig = lane & 3;
    int b0 = blockIdx.x * 64;

    // stage B = emb = [h | ht] split bf16
    for (int i = tid; i < 8192; i += 256) {
        int n = i >> 7, kp = i & 127;
        int k = kp * 2;
        float2 v = (k < 128) ? *(const float2*)(mem + (b0 + n) * 256 + k)
                             : *(const float2*)(g_ht + (b0 + n) * 128 + (k - 128));
        float h0 = __bfloat162float(__float2bfloat16(v.x));
        float h1 = __bfloat162float(__float2bfloat16(v.y));
        bhi[n * 132 + kp] = packbf(h0, h1);
        blo[n * 132 + kp] = packbf(v.x - h0, v.y - h1);
    }
    int j0 = w * 16 + gid;
    float bb[4][2];
    #pragma unroll
    for (int g = 0; g < 4; g++) {
        int jf = (g & 1) * 128 + j0;
        const float* bias = (g < 2) ? ab1 : cb1;
        bb[g][0] = bias[jf];
        bb[g][1] = bias[jf + 8];
    }
    __syncthreads();

    // layer 1: M=512 ([aw1;cw1]), K=256, N=64
    #pragma unroll
    for (int half = 0; half < 2; half++) {
        float D[4][4][4];
        #pragma unroll
        for (int g = 0; g < 4; g++)
            #pragma unroll
            for (int nt = 0; nt < 4; nt++)
                #pragma unroll
                for (int r = 0; r < 4; r++) D[g][nt][r] = 0.f;

        #pragma unroll
        for (int ks = 0; ks < 16; ks++) {
            uint32_t B0h[4], B1h[4], B0l[4], B1l[4];
            #pragma unroll
            for (int nt = 0; nt < 4; nt++) {
                int n = (half * 4 + nt) * 8 + gid;
                int kp = ks * 8 + tig;
                B0h[nt] = bhi[n * 132 + kp]; B1h[nt] = bhi[n * 132 + kp + 4];
                B0l[nt] = blo[n * 132 + kp]; B1l[nt] = blo[n * 132 + kp + 4];
            }
            #pragma unroll
            for (int g = 0; g < 4; g++) {
                uint32_t Ah[4], Al[4];
                uint32_t foff = (((uint32_t)(g * 8 + w) * 16 + ks) << 7) + lane * 4;
                *(uint4*)Ah = *(const uint4*)(g_hfragHi + foff);
                *(uint4*)Al = *(const uint4*)(g_hfragLo + foff);
                #pragma unroll
                for (int nt = 0; nt < 4; nt++) {
                    mma_bf16(D[g][nt], Ah, B0h[nt], B1h[nt]);
                    mma_bf16(D[g][nt], Ah, B0l[nt], B1l[nt]);
                    mma_bf16(D[g][nt], Al, B0h[nt], B1h[nt]);
                }
            }
        }
        // write tanh(a1) to smem (actor: g=0,1 ; critic: g=2,3)
        #pragma unroll
        for (int g = 0; g < 4; g++) {
            float* dst = (g < 2) ? a1a : a1c;
            #pragma unroll
            for (int nt = 0; nt < 4; nt++) {
                #pragma unroll
                for (int c = 0; c < 2; c++) {
                    int n = (half * 4 + nt) * 8 + tig * 2 + c;
                    #pragma unroll
                    for (int jj = 0; jj < 2; jj++) {
                        int jf = (g & 1) * 128 + j0 + jj * 8;
                        dst[n * 264 + jf] = tanh_(bb[g][jj] + D[g][nt][jj * 2 + c]);
                    }
                }
            }
        }
    }
    __syncthreads();

    // layer 2: warp w handles batches [w*8, w*8+8)
    for (int n = w * 8; n < w * 8 + 8; n++) {
        #pragma unroll
        for (int a = 0; a < 7; a++) {
            float s = 0.f;
            #pragma unroll
            for (int q = 0; q < 8; q++) {
                int k = lane + q * 32;
                s += aw2[a * 256 + k] * a1a[n * 264 + k];
            }
            #pragma unroll
            for (int off = 16; off; off >>= 1) s += __shfl_xor_sync(0xffffffffu, s, off);
            if (lane == 0) slog[n * 8 + a] = s + ab2[a];
        }
        {
            float s = 0.f;
            #pragma unroll
            for (int q = 0; q < 8; q++) {
                int k = lane + q * 32;
                s += cw2[k] * a1c[n * 264 + k];
            }
            #pragma unroll
            for (int off = 16; off; off >>= 1) s += __shfl_xor_sync(0xffffffffu, s, off);
            if (lane == 0) value[b0 + n] = s + cb2[0];
        }
    }
    __syncthreads();

    // log_softmax
    if (tid < 64) {
        float m = -1e30f;
        #pragma unroll
        for (int a = 0; a < 7; a++) m = fmaxf(m, slog[tid * 8 + a]);
        float sum = 0.f;
        #pragma unroll
        for (int a = 0; a < 7; a++) sum += expf(slog[tid * 8 + a] - m);
        float lse = m + logf(sum);
        #pragma unroll
        for (int a = 0; a < 7; a++) lp[(b0 + tid) * 7 + a] = slog[tid * 8 + a] - lse;
    }
}

// ---------------- launch ----------------
extern "C" void kernel_launch(void* const* d_in, const int* in_sizes, int n_in,
                              void* d_out, int out_size) {
    const int*   image  = (const int*)  d_in[0];
    const float* memory = (const float*)d_in[1];
    const int*   text   = (const int*)  d_in[2];
    const float* obj_e  = (const float*)d_in[3];
    const float* col_e  = (const float*)d_in[4];
    const float* st_e   = (const float*)d_in[5];
    const float* c1w    = (const float*)d_in[6];
    const float* c1b    = (const float*)d_in[7];
    const float* c2w    = (const float*)d_in[8];
    const float* c2b    = (const float*)d_in[9];
    const float* c3w    = (const float*)d_in[10];
    const float* c3b    = (const float*)d_in[11];
    const float* lwih   = (const float*)d_in[12];
    const float* lwhh   = (const float*)d_in[13];
    const float* lbih   = (const float*)d_in[14];
    const float* lbhh   = (const float*)d_in[15];
    const float* wemb   = (const float*)d_in[16];
    const float* gwih   = (const float*)d_in[17];
    const float* gwhh   = (const float*)d_in[18];
    const float* gbih   = (const float*)d_in[19];
    const float* gbhh   = (const float*)d_in[20];
    const float* aw1    = (const float*)d_in[21];
    const float* ab1    = (const float*)d_in[22];
    const float* aw2    = (const float*)d_in[23];
    const float* ab2    = (const float*)d_in[24];
    const float* cw1    = (const float*)d_in[25];
    const float* cb1    = (const float*)d_in[26];
    const float* cw2    = (const float*)d_in[27];
    const float* cb2    = (const float*)d_in[28];

    const int B = in_sizes[1] / 256;
    float* out   = (float*)d_out;
    float* lp    = out;
    float* value = out + (size_t)B * 7;
    float* memo  = out + (size_t)B * 8;

    uint32_t *lfH, *lfL, *hfH, *hfL;
    cudaGetSymbolAddress((void**)&lfH, g_lfragHi);
    cudaGetSymbolAddress((void**)&lfL, g_lfragLo);
    cudaGetSymbolAddress((void**)&hfH, g_hfragHi);
    cudaGetSymbolAddress((void**)&hfL, g_hfragLo);

    cudaFuncSetAttribute(k_gru_mma, cudaFuncAttributeMaxDynamicSharedMemorySize, GQ_SZ);
    cudaFuncSetAttribute(k_lstm_mma, cudaFuncAttributeMaxDynamicSharedMemorySize, LS_SZ);
    cudaFuncSetAttribute(k_heads_mma, cudaFuncAttributeMaxDynamicSharedMemorySize, HS_SZ);

    dim3 pgrid(64, 2);
    k_prep<<<pgrid, 256>>>(c2w, c3w);
    k_prep_frag<<<96, 256>>>(gwhh);
    k_prep_frag512<<<256, 256>>>(lwih, lwhh, lfH, lfL, 0);
    k_prep_frag512<<<256, 256>>>(aw1, cw1, hfH, hfL, 1);
    k_build_t1<<<4 * 132, 64>>>(obj_e, col_e, st_e, c1w);
    k_build_gi<<<100, 384>>>(wemb, gwih, gbih, gbhh);

    k_conv<<<B / 4, 128>>>(image, c1b, c2b, c3b);
    k_lstm_mma<<<B / 64, 256, LS_SZ>>>(memory, lbih, lbhh, memo);
    k_gru_mma<<<B / 64, 256, GQ_SZ>>>(text);
    k_heads_mma<<<B / 64, 256, HS_SZ>>>(memo, ab1, aw2, ab2, cb1, cw2, cb2, lp, value);
}

// round 13
// speedup vs baseline: 2.6275x; 1.6175x over previous
#include <cuda_runtime.h>
#include <cuda_bf16.h>
#include <cstdint>

// ---------------- scratch ----------------
__device__ __align__(16) float g_T1[4 * 132 * 64];
__device__ __align__(16) float g_GI2[100 * 512];   // [word][j][4]={r,z,n,pad}, bhh baked
__device__ __align__(16) float g_ht[8192 * 128];
__device__ __align__(16) float g_x[8192 * 128];
__device__ __align__(16) float g_w2T[64 * 256];
__device__ __align__(16) float g_w3T[128 * 256];
__device__ __align__(16) uint32_t g_wfragHi[3 * 8 * 8 * 32 * 4];
__device__ __align__(16) uint32_t g_wfragLo[3 * 8 * 8 * 32 * 4];
__device__ __align__(16) uint32_t g_lfragHi[4 * 8 * 16 * 32 * 4];
__device__ __align__(16) uint32_t g_lfragLo[4 * 8 * 16 * 32 * 4];
__device__ __align__(16) uint32_t g_hfragHi[4 * 8 * 16 * 32 * 4];
__device__ __align__(16) uint32_t g_hfragLo[4 * 8 * 16 * 32 * 4];

__device__ __forceinline__ float tanha_(float x) {
    float y; asm("tanh.approx.f32 %0, %1;" : "=f"(y) : "f"(x)); return y;
}
__device__ __forceinline__ float sigma_(float x) {
    return fmaf(tanha_(0.5f * x), 0.5f, 0.5f);
}

__device__ __forceinline__ void mma_bf16(float* d, const uint32_t* a, uint32_t b0, uint32_t b1) {
    asm volatile("mma.sync.aligned.m16n8k16.row.col.f32.bf16.bf16.f32 "
        "{%0,%1,%2,%3}, {%4,%5,%6,%7}, {%8,%9}, {%0,%1,%2,%3};"
        : "+f"(d[0]), "+f"(d[1]), "+f"(d[2]), "+f"(d[3])
        : "r"(a[0]), "r"(a[1]), "r"(a[2]), "r"(a[3]), "r"(b0), "r"(b1));
}
__device__ __forceinline__ uint32_t packbf(float a, float b) {
    __nv_bfloat16 ha = __float2bfloat16(a), hb = __float2bfloat16(b);
    return (uint32_t)*(uint16_t*)&ha | ((uint32_t)*(uint16_t*)&hb << 16);
}

// ---------------- P1: all mma fragments (608 blocks x 256) ----------------
__global__ void k_prep_frags(const float* __restrict__ gwhh,
                             const float* __restrict__ lwih, const float* __restrict__ lwhh,
                             const float* __restrict__ aw1, const float* __restrict__ cw1) {
    int blk = blockIdx.x;
    if (blk < 96) {                       // GRU whh frags
        int idx = blk * 256 + threadIdx.x;
        int r = idx & 3, lane = (idx >> 2) & 31, ks = (idx >> 7) & 7;
        int w = (idx >> 10) & 7, g = idx >> 13;
        int gid = lane >> 2, tig = lane & 3;
        int row = w * 16 + gid + ((r & 1) ? 8 : 0);
        int col = ks * 16 + tig * 2 + ((r & 2) ? 8 : 0);
        float w0 = gwhh[(g * 128 + row) * 128 + col];
        float w1 = gwhh[(g * 128 + row) * 128 + col + 1];
        float h0 = __bfloat162float(__float2bfloat16(w0));
        float h1 = __bfloat162float(__float2bfloat16(w1));
        g_wfragHi[idx] = packbf(h0, h1);
        g_wfragLo[idx] = packbf(w0 - h0, w1 - h1);
    } else {                              // 512x256 frags: LSTM (mode0), heads (mode1)
        int seg = blk - 96;
        int mode = seg >> 8;              // 0: lstm, 1: heads
        int idx = (seg & 255) * 256 + threadIdx.x;
        int r = idx & 3, lane = (idx >> 2) & 31, ks = (idx >> 7) & 15;
        int w = (idx >> 11) & 7, g = idx >> 14;
        int gid = lane >> 2, tig = lane & 3;
        int m = g * 128 + w * 16 + gid + ((r & 1) ? 8 : 0);
        int col = ks * 16 + tig * 2 + ((r & 2) ? 8 : 0);
        float w0, w1;
        if (mode == 0) {
            if (col < 128) { w0 = lwih[m * 128 + col];       w1 = lwih[m * 128 + col + 1]; }
            else           { w0 = lwhh[m * 128 + col - 128]; w1 = lwhh[m * 128 + col - 127]; }
        } else {
            const float* src = (m < 256) ? aw1 : cw1;
            int mm = (m < 256) ? m : m - 256;
            w0 = src[mm * 256 + col]; w1 = src[mm * 256 + col + 1];
        }
        float h0 = __bfloat162float(__float2bfloat16(w0));
        float h1 = __bfloat162float(__float2bfloat16(w1));
        uint32_t* dHi = mode ? g_hfragHi : g_lfragHi;
        uint32_t* dLo = mode ? g_hfragLo : g_lfragLo;
        dHi[idx] = packbf(h0, h1);
        dLo[idx] = packbf(w0 - h0, w1 - h1);
    }
}

// ---------------- P2: T1 table + GI table (232 blocks x 256) ----------------
__global__ void k_prep_tables(const float* __restrict__ obj_emb, const float* __restrict__ col_emb,
                              const float* __restrict__ st_emb, const float* __restrict__ w1,
                              const float* __restrict__ word_emb, const float* __restrict__ gwih,
                              const float* __restrict__ gbih, const float* __restrict__ gbhh) {
    int blk = blockIdx.x, t = threadIdx.x;
    if (blk < 132) {                      // T1: combo = blk, 4 taps x 64 oc
        int combo = blk;
        int s = combo & 1, q = combo >> 1;
        int cc = q % 6, o = q / 6;
        __shared__ __align__(16) float ev[48];
        if (t < 16)       ev[t] = col_emb[cc * 16 + t];
        else if (t < 32)  ev[t] = obj_emb[o * 16 + (t - 16)];
        else if (t < 48)  ev[t] = st_emb[s * 16 + (t - 32)];
        __syncthreads();
        int tap = t >> 6, oc = t & 63;
        int ty = tap >> 1, tx = tap & 1;
        float v = 0.f;
        #pragma unroll 8
        for (int k = 0; k < 48; k++) v += w1[((oc * 48 + k) * 2 + ty) * 2 + tx] * ev[k];
        g_T1[(tap * 132 + combo) * 64 + oc] = v;
    } else {                              // GI: word = blk-132
        int v = blk - 132;
        __shared__ __align__(16) float ev[32];
        if (t < 32) ev[t] = word_emb[v * 32 + t];
        __syncthreads();
        for (int g = t; g < 384; g += 256) {
            float a = gbih[g] + gbhh[g];
            const float* w = gwih + g * 32;
            #pragma unroll 8
            for (int k = 0; k < 32; k++) a += w[k] * ev[k];
            int gate = g >> 7, j = g & 127;
            g_GI2[v * 512 + j * 4 + gate] = a;
        }
    }
}

// ---------------- P3: conv weight transpose (192 blocks x 256) ----------------
__global__ void k_prep_w(const float* __restrict__ c2w, const float* __restrict__ c3w) {
    int idx = blockIdx.x * 256 + threadIdx.x;   // 49152 total
    if (idx < 16384) {
        int j = idx / 256, k = idx % 256;
        g_w2T[(k >> 2) * 256 + j * 4 + (k & 3)] = c2w[idx];
    } else {
        int i2 = idx - 16384;
        int j = i2 / 256, k = i2 % 256;
        g_w3T[(k >> 2) * 512 + j * 4 + (k & 3)] = c3w[i2];
    }
}

// ---------------- K3: conv stack (4 elems/block, 128 thr) ----------------
__global__ __launch_bounds__(128)
void k_conv(const int* __restrict__ image, const float* __restrict__ b1,
            const float* __restrict__ b2, const float* __restrict__ b3) {
    int t = threadIdx.x;
    int b0 = blockIdx.x * 4;
    __shared__ __align__(16) int   s_combo[4][49];
    __shared__ __align__(16) float s_c1[4][36 * 64];
    __shared__ __align__(16) float s_p[4][9 * 64];
    __shared__ __align__(16) float s_q[4][4 * 64];

    for (int i = t; i < 196; i += 128) {
        int e = i / 49, li = i % 49;
        const int* px = image + ((b0 + e) * 49 + li) * 3;
        s_combo[e][li] = (px[0] * 6 + px[1]) * 2 + px[2];
    }
    __syncthreads();
    for (int idx = t; idx < 2304; idx += 128) {
        int c = idx & 63, pos = idx >> 6;
        int y = pos / 6, x = pos % 6;
        float bb = b1[c];
        #pragma unroll
        for (int e = 0; e < 4; e++) {
            float v = bb;
            v += g_T1[(0 * 132 + s_combo[e][y * 7 + x]) * 64 + c];
            v += g_T1[(1 * 132 + s_combo[e][y * 7 + x + 1]) * 64 + c];
            v += g_T1[(2 * 132 + s_combo[e][(y + 1) * 7 + x]) * 64 + c];
            v += g_T1[(3 * 132 + s_combo[e][(y + 1) * 7 + x + 1]) * 64 + c];
            s_c1[e][pos * 64 + c] = fmaxf(v, 0.f);
        }
    }
    __syncthreads();
    for (int idx = t; idx < 576; idx += 128) {
        int c = idx & 63, pos = idx >> 6;
        int y = pos / 3, x = pos % 3;
        int p0 = (2 * y) * 6 + 2 * x;
        #pragma unroll
        for (int e = 0; e < 4; e++)
            s_p[e][pos * 64 + c] =
                fmaxf(fmaxf(s_c1[e][p0 * 64 + c], s_c1[e][(p0 + 1) * 64 + c]),
                      fmaxf(s_c1[e][(p0 + 6) * 64 + c], s_c1[e][(p0 + 7) * 64 + c]));
    }
    __syncthreads();
    for (int idx = t; idx < 256; idx += 128) {
        int c = idx & 63, pos = idx >> 6;
        int y = pos >> 1, x = pos & 1;
        int p00 = y * 3 + x;
        float v[4];
        float bb = b2[c];
        #pragma unroll
        for (int e = 0; e < 4; e++) v[e] = bb;
        #pragma unroll 4
        for (int ci = 0; ci < 64; ci++) {
            float4 w4 = *(const float4*)(g_w2T + ci * 256 + c * 4);
            #pragma unroll
            for (int e = 0; e < 4; e++)
                v[e] += w4.x * s_p[e][p00 * 64 + ci] + w4.y * s_p[e][(p00 + 1) * 64 + ci]
                      + w4.z * s_p[e][(p00 + 3) * 64 + ci] + w4.w * s_p[e][(p00 + 4) * 64 + ci];
        }
        #pragma unroll
        for (int e = 0; e < 4; e++) s_q[e][pos * 64 + c] = fmaxf(v[e], 0.f);
    }
    __syncthreads();
    {
        float v[4];
        float bb = b3[t];
        #pragma unroll
        for (int e = 0; e < 4; e++) v[e] = bb;
        #pragma unroll 4
        for (int ci = 0; ci < 64; ci++) {
            float4 w4 = *(const float4*)(g_w3T + ci * 512 + t * 4);
            #pragma unroll
            for (int e = 0; e < 4; e++)
                v[e] += w4.x * s_q[e][0 * 64 + ci] + w4.y * s_q[e][1 * 64 + ci]
                      + w4.z * s_q[e][2 * 64 + ci] + w4.w * s_q[e][3 * 64 + ci];
        }
        #pragma unroll
        for (int e = 0; e < 4; e++) g_x[(b0 + e) * 128 + t] = fmaxf(v[e], 0.f);
    }
}

// ---------------- K4: mma.sync LSTM (64 batch/block, 256 thr) ----------------
static constexpr int LS_SZ = 67584;

__global__ __launch_bounds__(256)
void k_lstm_mma(const float* __restrict__ memory, const float* __restrict__ bih,
                const float* __restrict__ bhh, float* __restrict__ mem_out) {
    extern __shared__ __align__(16) char smem[];
    uint32_t* bhi = (uint32_t*)smem;
    uint32_t* blo = bhi + 64 * 132;
    int tid = threadIdx.x;
    int w = tid >> 5, lane = tid & 31;
    int gid = lane >> 2, tig = lane & 3;
    int b0 = blockIdx.x * 64;

    for (int i = tid; i < 8192; i += 256) {
        int n = i >> 7, kp = i & 127;
        int k = kp * 2;
        float2 v = (k < 128) ? *(const float2*)(g_x + (b0 + n) * 128 + k)
                             : *(const float2*)(memory + (b0 + n) * 256 + (k - 128));
        float h0 = __bfloat162float(__float2bfloat16(v.x));
        float h1 = __bfloat162float(__float2bfloat16(v.y));
        bhi[n * 132 + kp] = packbf(h0, h1);
        blo[n * 132 + kp] = packbf(v.x - h0, v.y - h1);
    }
    int j0 = w * 16 + gid;
    float bb[4][2];
    #pragma unroll
    for (int g = 0; g < 4; g++) {
        bb[g][0] = bih[g * 128 + j0] + bhh[g * 128 + j0];
        bb[g][1] = bih[g * 128 + j0 + 8] + bhh[g * 128 + j0 + 8];
    }
    __syncthreads();

    #pragma unroll
    for (int half = 0; half < 2; half++) {
        float D[4][4][4];
        #pragma unroll
        for (int g = 0; g < 4; g++)
            #pragma unroll
            for (int nt = 0; nt < 4; nt++)
                #pragma unroll
                for (int r = 0; r < 4; r++) D[g][nt][r] = 0.f;

        #pragma unroll
        for (int ks = 0; ks < 16; ks++) {
            uint32_t B0h[4], B1h[4], B0l[4], B1l[4];
            #pragma unroll
            for (int nt = 0; nt < 4; nt++) {
                int n = (half * 4 + nt) * 8 + gid;
                int kp = ks * 8 + tig;
                B0h[nt] = bhi[n * 132 + kp]; B1h[nt] = bhi[n * 132 + kp + 4];
                B0l[nt] = blo[n * 132 + kp]; B1l[nt] = blo[n * 132 + kp + 4];
            }
            #pragma unroll
            for (int g = 0; g < 4; g++) {
                uint32_t Ah[4], Al[4];
                uint32_t foff = (((uint32_t)(g * 8 + w) * 16 + ks) << 7) + lane * 4;
                *(uint4*)Ah = *(const uint4*)(g_lfragHi + foff);
                *(uint4*)Al = *(const uint4*)(g_lfragLo + foff);
                #pragma unroll
                for (int nt = 0; nt < 4; nt++) {
                    mma_bf16(D[g][nt], Ah, B0h[nt], B1h[nt]);
                    mma_bf16(D[g][nt], Ah, B0l[nt], B1l[nt]);
                    mma_bf16(D[g][nt], Al, B0h[nt], B1h[nt]);
                }
            }
        }
        #pragma unroll
        for (int nt = 0; nt < 4; nt++) {
            #pragma unroll
            for (int c = 0; c < 2; c++) {
                int n = (half * 4 + nt) * 8 + tig * 2 + c;
                #pragma unroll
                for (int jj = 0; jj < 2; jj++) {
                    int j = j0 + jj * 8;
                    int reg = jj * 2 + c;
                    float gi_ = bb[0][jj] + D[0][nt][reg];
                    float gf  = bb[1][jj] + D[1][nt][reg];
                    float gg  = bb[2][jj] + D[2][nt][reg];
                    float go  = bb[3][jj] + D[3][nt][reg];
                    float c_in = memory[(b0 + n) * 256 + 128 + j];
                    float cn = sigma_(gf) * c_in + sigma_(gi_) * tanha_(gg);
                    float hn = sigma_(go) * tanha_(cn);
                    mem_out[(b0 + n) * 256 + j] = hn;
                    mem_out[(b0 + n) * 256 + 128 + j] = cn;
                }
            }
        }
    }
}

// ---------------- K5: mma.sync GRU (64 batch/block, 256 thr) ----------------
static constexpr int GQ_WHI = 0;
static constexpr int GQ_WLO = 98304;
static constexpr int GQ_BHI = 196608;
static constexpr int GQ_BLO = 196608 + 17408;
static constexpr int GQ_SZ  = 196608 + 34816;

__global__ __launch_bounds__(256, 1)
void k_gru_mma(const int* __restrict__ text) {
    extern __shared__ __align__(16) char smem[];
    int tid = threadIdx.x;
    int w = tid >> 5, lane = tid & 31;
    int gid = lane >> 2, tig = lane & 3;
    int b0 = blockIdx.x * 64;

    {
        const uint4* s1 = (const uint4*)g_wfragHi;
        const uint4* s2 = (const uint4*)g_wfragLo;
        uint4* d1 = (uint4*)(smem + GQ_WHI);
        uint4* d2 = (uint4*)(smem + GQ_WLO);
        for (int i = tid; i < 6144; i += 256) { d1[i] = s1[i]; d2[i] = s2[i]; }
        uint4 z = make_uint4(0, 0, 0, 0);
        uint4* dz = (uint4*)(smem + GQ_BHI);
        for (int i = tid; i < 2176; i += 256) dz[i] = z;
    }
    __syncthreads();

    const uint32_t* bhi = (const uint32_t*)(smem + GQ_BHI);
    const uint32_t* blo = (const uint32_t*)(smem + GQ_BLO);

    for (int tt = 0; tt < 20; tt++) {
        // prefetch this step's words (latency hidden under MMA phase)
        int words[16];
        #pragma unroll
        for (int nt = 0; nt < 8; nt++)
            #pragma unroll
            for (int c = 0; c < 2; c++)
                words[nt * 2 + c] = text[(b0 + nt * 8 + tig * 2 + c) * 20 + tt];

        float D[3][8][4];
        #pragma unroll
        for (int g = 0; g < 3; g++)
            #pragma unroll
            for (int nt = 0; nt < 8; nt++)
                #pragma unroll
                for (int r = 0; r < 4; r++) D[g][nt][r] = 0.f;

        #pragma unroll
        for (int ks = 0; ks < 8; ks++) {
            uint32_t B0h[8], B1h[8], B0l[8], B1l[8];
            #pragma unroll
            for (int nt = 0; nt < 8; nt++) {
                int n = nt * 8 + gid;
                int kp = ks * 8 + tig;
                B0h[nt] = bhi[n * 68 + kp];  B1h[nt] = bhi[n * 68 + kp + 4];
                B0l[nt] = blo[n * 68 + kp];  B1l[nt] = blo[n * 68 + kp + 4];
            }
            #pragma unroll
            for (int g = 0; g < 3; g++) {
                uint32_t Ah[4], Al[4];
                uint32_t foff = (((uint32_t)(g * 8 + w) * 8 + ks) << 9) + lane * 16;
                *(uint4*)Ah = *(const uint4*)(smem + GQ_WHI + foff);
                *(uint4*)Al = *(const uint4*)(smem + GQ_WLO + foff);
                #pragma unroll
                for (int nt = 0; nt < 8; nt++) {
                    mma_bf16(D[g][nt], Ah, B0h[nt], B1h[nt]);
                    mma_bf16(D[g][nt], Ah, B0l[nt], B1l[nt]);
                    mma_bf16(D[g][nt], Al, B0h[nt], B1h[nt]);
                }
            }
        }
        __syncthreads();

        #pragma unroll
        for (int nt = 0; nt < 8; nt++) {
            #pragma unroll
            for (int c = 0; c < 2; c++) {
                int n = nt * 8 + tig * 2 + c;
                const float4* gi4 = (const float4*)(g_GI2 + words[nt * 2 + c] * 512);
                #pragma unroll
                for (int jj = 0; jj < 2; jj++) {
                    int j = w * 16 + gid + jj * 8;
                    int reg = jj * 2 + c;
                    float4 gv = gi4[j];
                    uint32_t boff = (uint32_t)(n * 68 + (j >> 1)) * 4 + (uint32_t)(j & 1) * 2;
                    float hp = __bfloat162float(*(__nv_bfloat16*)(smem + GQ_BHI + boff))
                             + __bfloat162float(*(__nv_bfloat16*)(smem + GQ_BLO + boff));
                    float r = sigma_(gv.x + D[0][nt][reg]);
                    float z = sigma_(gv.y + D[1][nt][reg]);
                    float nv = tanha_(gv.z + r * D[2][nt][reg]);
                    float h = (1.f - z) * nv + z * hp;
                    __nv_bfloat16 hhi = __float2bfloat16(h);
                    *(__nv_bfloat16*)(smem + GQ_BHI + boff) = hhi;
                    *(__nv_bfloat16*)(smem + GQ_BLO + boff) =
                        __float2bfloat16(h - __bfloat162float(hhi));
                    if (tt == 19) g_ht[(b0 + n) * 128 + j] = h;
                }
            }
        }
        __syncthreads();
    }
}

// ---------------- K6: mma.sync heads (64 batch/block, 256 thr) ----------------
static constexpr int HS_BHI = 0;
static constexpr int HS_BLO = 33792;
static constexpr int HS_A1A = 67584;
static constexpr int HS_A1C = 135168;
static constexpr int HS_LOG = 202752;
static constexpr int HS_SZ  = 204800;

__global__ __launch_bounds__(256, 1)
void k_heads_mma(const float* __restrict__ mem,
                 const float* __restrict__ ab1, const float* __restrict__ aw2,
                 const float* __restrict__ ab2, const float* __restrict__ cb1,
                 const float* __restrict__ cw2, const float* __restrict__ cb2,
                 float* __restrict__ lp, float* __restrict__ value) {
    extern __shared__ __align__(16) char smem[];
    uint32_t* bhi = (uint32_t*)(smem + HS_BHI);
    uint32_t* blo = (uint32_t*)(smem + HS_BLO);
    float* a1a = (float*)(smem + HS_A1A);
    float* a1c = (float*)(smem + HS_A1C);
    float* slog = (float*)(smem + HS_LOG);
    int tid = threadIdx.x;
    int w = tid >> 5, lane = tid & 31;
    int gid = lane >> 2, tig = lane & 3;
    int b0 = blockIdx.x * 64;

    for (int i = tid; i < 8192; i += 256) {
        int n = i >> 7, kp = i & 127;
        int k = kp * 2;
        float2 v = (k < 128) ? *(const float2*)(mem + (b0 + n) * 256 + k)
                             : *(const float2*)(g_ht + (b0 + n) * 128 + (k - 128));
        float h0 = __bfloat162float(__float2bfloat16(v.x));
        float h1 = __bfloat162float(__float2bfloat16(v.y));
        bhi[n * 132 + kp] = packbf(h0, h1);
        blo[n * 132 + kp] = packbf(v.x - h0, v.y - h1);
    }
    int j0 = w * 16 + gid;
    float bb[4][2];
    #pragma unroll
    for (int g = 0; g < 4; g++) {
        int jf = (g & 1) * 128 + j0;
        const float* bias = (g < 2) ? ab1 : cb1;
        bb[g][0] = bias[jf];
        bb[g][1] = bias[jf + 8];
    }
    __syncthreads();

    #pragma unroll
    for (int half = 0; half < 2; half++) {
        float D[4][4][4];
        #pragma unroll
        for (int g = 0; g < 4; g++)
            #pragma unroll
            for (int nt = 0; nt < 4; nt++)
                #pragma unroll
                for (int r = 0; r < 4; r++) D[g][nt][r] = 0.f;

        #pragma unroll
        for (int ks = 0; ks < 16; ks++) {
            uint32_t B0h[4], B1h[4], B0l[4], B1l[4];
            #pragma unroll
            for (int nt = 0; nt < 4; nt++) {
                int n = (half * 4 + nt) * 8 + gid;
                int kp = ks * 8 + tig;
                B0h[nt] = bhi[n * 132 + kp]; B1h[nt] = bhi[n * 132 + kp + 4];
                B0l[nt] = blo[n * 132 + kp]; B1l[nt] = blo[n * 132 + kp + 4];
            }
            #pragma unroll
            for (int g = 0; g < 4; g++) {
                uint32_t Ah[4], Al[4];
                uint32_t foff = (((uint32_t)(g * 8 + w) * 16 + ks) << 7) + lane * 4;
                *(uint4*)Ah = *(const uint4*)(g_hfragHi + foff);
                *(uint4*)Al = *(const uint4*)(g_hfragLo + foff);
                #pragma unroll
                for (int nt = 0; nt < 4; nt++) {
                    mma_bf16(D[g][nt], Ah, B0h[nt], B1h[nt]);
                    mma_bf16(D[g][nt], Ah, B0l[nt], B1l[nt]);
                    mma_bf16(D[g][nt], Al, B0h[nt], B1h[nt]);
                }
            }
        }
        #pragma unroll
        for (int g = 0; g < 4; g++) {
            float* dst = (g < 2) ? a1a : a1c;
            #pragma unroll
            for (int nt = 0; nt < 4; nt++) {
                #pragma unroll
                for (int c = 0; c < 2; c++) {
                    int n = (half * 4 + nt) * 8 + tig * 2 + c;
                    #pragma unroll
                    for (int jj = 0; jj < 2; jj++) {
                        int jf = (g & 1) * 128 + j0 + jj * 8;
                        dst[n * 264 + jf] = tanha_(bb[g][jj] + D[g][nt][jj * 2 + c]);
                    }
                }
            }
        }
    }
    __syncthreads();

    for (int n = w * 8; n < w * 8 + 8; n++) {
        #pragma unroll
        for (int a = 0; a < 7; a++) {
            float s = 0.f;
            #pragma unroll
            for (int q = 0; q < 8; q++) {
                int k = lane + q * 32;
                s += aw2[a * 256 + k] * a1a[n * 264 + k];
            }
            #pragma unroll
            for (int off = 16; off; off >>= 1) s += __shfl_xor_sync(0xffffffffu, s, off);
            if (lane == 0) slog[n * 8 + a] = s + ab2[a];
        }
        {
            float s = 0.f;
            #pragma unroll
            for (int q = 0; q < 8; q++) {
                int k = lane + q * 32;
                s += cw2[k] * a1c[n * 264 + k];
            }
            #pragma unroll
            for (int off = 16; off; off >>= 1) s += __shfl_xor_sync(0xffffffffu, s, off);
            if (lane == 0) value[b0 + n] = s + cb2[0];
        }
    }
    __syncthreads();

    if (tid < 64) {
        float m = -1e30f;
        #pragma unroll
        for (int a = 0; a < 7; a++) m = fmaxf(m, slog[tid * 8 + a]);
        float sum = 0.f;
        #pragma unroll
        for (int a = 0; a < 7; a++) sum += expf(slog[tid * 8 + a] - m);
        float lse = m + logf(sum);
        #pragma unroll
        for (int a = 0; a < 7; a++) lp[(b0 + tid) * 7 + a] = slog[tid * 8 + a] - lse;
    }
}

// ---------------- launch ----------------
extern "C" void kernel_launch(void* const* d_in, const int* in_sizes, int n_in,
                              void* d_out, int out_size) {
    const int*   image  = (const int*)  d_in[0];
    const float* memory = (const float*)d_in[1];
    const int*   text   = (const int*)  d_in[2];
    const float* obj_e  = (const float*)d_in[3];
    const float* col_e  = (const float*)d_in[4];
    const float* st_e   = (const float*)d_in[5];
    const float* c1w    = (const float*)d_in[6];
    const float* c1b    = (const float*)d_in[7];
    const float* c2w    = (const float*)d_in[8];
    const float* c2b    = (const float*)d_in[9];
    const float* c3w    = (const float*)d_in[10];
    const float* c3b    = (const float*)d_in[11];
    const float* lwih   = (const float*)d_in[12];
    const float* lwhh   = (const float*)d_in[13];
    const float* lbih   = (const float*)d_in[14];
    const float* lbhh   = (const float*)d_in[15];
    const float* wemb   = (const float*)d_in[16];
    const float* gwih   = (const float*)d_in[17];
    const float* gwhh   = (const float*)d_in[18];
    const float* gbih   = (const float*)d_in[19];
    const float* gbhh   = (const float*)d_in[20];
    const float* aw1    = (const float*)d_in[21];
    const float* ab1    = (const float*)d_in[22];
    const float* aw2    = (const float*)d_in[23];
    const float* ab2    = (const float*)d_in[24];
    const float* cw1    = (const float*)d_in[25];
    const float* cb1    = (const float*)d_in[26];
    const float* cw2    = (const float*)d_in[27];
    const float* cb2    = (const float*)d_in[28];

    const int B = in_sizes[1] / 256;
    float* out   = (float*)d_out;
    float* lp    = out;
    float* value = out + (size_t)B * 7;
    float* memo  = out + (size_t)B * 8;

    cudaFuncSetAttribute(k_gru_mma, cudaFuncAttributeMaxDynamicSharedMemorySize, GQ_SZ);
    cudaFuncSetAttribute(k_lstm_mma, cudaFuncAttributeMaxDynamicSharedMemorySize, LS_SZ);
    cudaFuncSetAttribute(k_heads_mma, cudaFuncAttributeMaxDynamicSharedMemorySize, HS_SZ);

    k_prep_frags<<<608, 256>>>(gwhh, lwih, lwhh, aw1, cw1);
    k_prep_tables<<<232, 256>>>(obj_e, col_e, st_e, c1w, wemb, gwih, gbih, gbhh);
    k_prep_w<<<192, 256>>>(c2w, c3w);

    k_conv<<<B / 4, 128>>>(image, c1b, c2b, c3b);
    k_lstm_mma<<<B / 64, 256, LS_SZ>>>(memory, lbih, lbhh, memo);
    k_gru_mma<<<B / 64, 256, GQ_SZ>>>(text);
    k_heads_mma<<<B / 64, 256, HS_SZ>>>(memo, ab1, aw2, ab2, cb1, cw2, cb2, lp, value);
}